// round 1
// baseline (speedup 1.0000x reference)
#include <cuda_runtime.h>
#include <math.h>

// Problem constants
#define TOK   4096      // 2 * 2048 tokens
#define NSEQ  2048
#define DIM   768
#define H3    2304      // 3*DIM
#define HID   3072
#define NHEAD 12
#define HD    64

// Scratch (no allocations allowed -> __device__ globals)
__device__ float g_h  [TOK * DIM];   // LN1 out
__device__ float g_qkv[TOK * H3];    // qkv
__device__ float g_o  [TOK * DIM];   // attention out
__device__ float g_x1 [TOK * DIM];   // x + proj
__device__ float g_h2 [TOK * DIM];   // LN2 out
__device__ float g_m  [TOK * HID];   // gelu(fc1)

// ---------------------------------------------------------------------------
// LayerNorm: one block per row of 768, 256 threads (3 elems/thread)
// ---------------------------------------------------------------------------
__global__ __launch_bounds__(256) void ln_kernel(
    const float* __restrict__ x, const float* __restrict__ g,
    const float* __restrict__ b, float* __restrict__ out)
{
    int row = blockIdx.x;
    int t   = threadIdx.x;
    const float* xr = x + row * DIM;

    float v0 = xr[t], v1 = xr[t + 256], v2 = xr[t + 512];
    float s = v0 + v1 + v2;
    float q = v0 * v0 + v1 * v1 + v2 * v2;

    __shared__ float rs[8], rq[8];
    #pragma unroll
    for (int o = 16; o; o >>= 1) {
        s += __shfl_xor_sync(0xffffffffu, s, o);
        q += __shfl_xor_sync(0xffffffffu, q, o);
    }
    if ((t & 31) == 0) { rs[t >> 5] = s; rq[t >> 5] = q; }
    __syncthreads();

    __shared__ float smu, srstd;
    if (t == 0) {
        float S = 0.f, Q = 0.f;
        #pragma unroll
        for (int i = 0; i < 8; i++) { S += rs[i]; Q += rq[i]; }
        float mu  = S * (1.0f / DIM);
        float var = Q * (1.0f / DIM) - mu * mu;
        smu = mu;
        srstd = rsqrtf(var + 1e-5f);
    }
    __syncthreads();
    float mu = smu, r = srstd;
    float* orow = out + row * DIM;
    orow[t]       = (v0 - mu) * r * g[t]       + b[t];
    orow[t + 256] = (v1 - mu) * r * g[t + 256] + b[t + 256];
    orow[t + 512] = (v2 - mu) * r * g[t + 512] + b[t + 512];
}

// ---------------------------------------------------------------------------
// SGEMM: C[M,N] = A[M,K] @ B[K,N]  (+ optional bias / residual / gelu)
// 128x128 block tile, BK=16, 256 threads, 8x8 micro-tile.
// EPI: 0 = none, 1 = bias + residual, 2 = bias + exact GELU
// All dims are exact multiples of the tiles for this problem (no bounds checks)
// ---------------------------------------------------------------------------
template<int EPI>
__global__ __launch_bounds__(256) void gemm_kernel(
    const float* __restrict__ A, const float* __restrict__ B,
    const float* __restrict__ bias, const float* __restrict__ res,
    float* __restrict__ C, int M, int N, int K)
{
    __shared__ float As[16][132];   // As[k][m], padded
    __shared__ float Bs[16][132];   // Bs[k][n], padded

    int tid = threadIdx.x;
    int tx  = tid & 15;          // 0..15  (col group)
    int ty  = tid >> 4;          // 0..15  (row group)
    int row0 = blockIdx.y * 128;
    int col0 = blockIdx.x * 128;

    const float* Ab = A + (size_t)row0 * K;
    const float* Bb = B + col0;

    float acc[8][8];
    #pragma unroll
    for (int i = 0; i < 8; i++)
        #pragma unroll
        for (int j = 0; j < 8; j++) acc[i][j] = 0.f;

    for (int k0 = 0; k0 < K; k0 += 16) {
        // Load A tile 128x16 (2048 elems, 8 per thread), store transposed As[k][m]
        #pragma unroll
        for (int i = 0; i < 8; i++) {
            int e = tid + i * 256;
            int r = e >> 4, c = e & 15;
            As[c][r] = Ab[(size_t)r * K + k0 + c];
        }
        // Load B tile 16x128 (coalesced rows of 128)
        #pragma unroll
        for (int i = 0; i < 8; i++) {
            int e = tid + i * 256;
            int r = e >> 7, c = e & 127;
            Bs[r][c] = Bb[(size_t)(k0 + r) * N + c];
        }
        __syncthreads();

        #pragma unroll
        for (int k = 0; k < 16; k++) {
            float4 a0 = *(const float4*)&As[k][ty * 8];
            float4 a1 = *(const float4*)&As[k][ty * 8 + 4];
            float4 b0 = *(const float4*)&Bs[k][tx * 8];
            float4 b1 = *(const float4*)&Bs[k][tx * 8 + 4];
            float a[8] = {a0.x, a0.y, a0.z, a0.w, a1.x, a1.y, a1.z, a1.w};
            float bb[8] = {b0.x, b0.y, b0.z, b0.w, b1.x, b1.y, b1.z, b1.w};
            #pragma unroll
            for (int i = 0; i < 8; i++)
                #pragma unroll
                for (int j = 0; j < 8; j++)
                    acc[i][j] = fmaf(a[i], bb[j], acc[i][j]);
        }
        __syncthreads();
    }

    // Epilogue
    #pragma unroll
    for (int i = 0; i < 8; i++) {
        int r = row0 + ty * 8 + i;
        #pragma unroll
        for (int j = 0; j < 8; j++) {
            int c = col0 + tx * 8 + j;
            float v = acc[i][j];
            if (EPI >= 1) v += bias[c];
            if (EPI == 1) v += res[(size_t)r * N + c];
            if (EPI == 2) v = 0.5f * v * (1.0f + erff(v * 0.70710678118f));
            C[(size_t)r * N + c] = v;
        }
    }
}

// ---------------------------------------------------------------------------
// Flash attention (fp32, online softmax).
// Grid: (32 q-tiles, 12 heads, 2 batch). 256 threads.
// Tiles: 64 queries x 64 keys, head_dim = 64 entirely in smem.
// Dynamic smem: Qs[64][65] + KsT[64][65] + Vs[64][65] + Ss[64][65] + 3*64
// ---------------------------------------------------------------------------
__global__ __launch_bounds__(256) void attn_kernel(
    const float* __restrict__ qkv, float* __restrict__ o)
{
    extern __shared__ float smem[];
    float* Qs      = smem;                 // [64][65]  Q rows (pre-scaled)
    float* KsT     = Qs  + 64 * 65;        // [d][n]    K transposed
    float* Vs      = KsT + 64 * 65;        // [n][d]
    float* Ss      = Vs  + 64 * 65;        // [64][65]  scores / probs
    float* alpha_s = Ss  + 64 * 65;        // [64]
    float* m_s     = alpha_s + 64;         // [64]
    float* l_s     = m_s + 64;             // [64]

    int tid = threadIdx.x;
    int tx  = tid & 15;    // col group (4 cols)
    int ty  = tid >> 4;    // row group (4 rows)

    int qt = blockIdx.x, h = blockIdx.y, b = blockIdx.z;
    int q_tok0 = b * NSEQ + qt * 64;
    int qcol = h * HD;
    int kcol = DIM + h * HD;
    int vcol = 2 * DIM + h * HD;
    const float scale = 0.125f;  // 1/sqrt(64)

    // Load Q tile (scale folded in)
    #pragma unroll
    for (int i = 0; i < 16; i++) {
        int e = tid + i * 256;
        int r = e >> 6, c = e & 63;
        Qs[r * 65 + c] = qkv[(size_t)(q_tok0 + r) * H3 + qcol + c] * scale;
    }
    if (tid < 64) { m_s[tid] = -1e30f; l_s[tid] = 0.f; }

    float Oa[4][4];
    #pragma unroll
    for (int i = 0; i < 4; i++)
        #pragma unroll
        for (int j = 0; j < 4; j++) Oa[i][j] = 0.f;

    for (int kt = 0; kt < NSEQ / 64; kt++) {
        int k_tok0 = b * NSEQ + kt * 64;
        __syncthreads();   // prev iter's consumers done; Q/m/l visible on iter 0
        #pragma unroll
        for (int i = 0; i < 16; i++) {
            int e = tid + i * 256;
            int r = e >> 6, c = e & 63;
            KsT[c * 65 + r] = qkv[(size_t)(k_tok0 + r) * H3 + kcol + c];
            Vs [r * 65 + c] = qkv[(size_t)(k_tok0 + r) * H3 + vcol + c];
        }
        __syncthreads();

        // S = Q @ K^T (scaled)
        float Sa[4][4];
        #pragma unroll
        for (int i = 0; i < 4; i++)
            #pragma unroll
            for (int j = 0; j < 4; j++) Sa[i][j] = 0.f;

        #pragma unroll 8
        for (int d = 0; d < 64; d++) {
            float qv[4], kv[4];
            #pragma unroll
            for (int i = 0; i < 4; i++) qv[i] = Qs[(ty * 4 + i) * 65 + d];
            #pragma unroll
            for (int j = 0; j < 4; j++) kv[j] = KsT[d * 65 + tx * 4 + j];
            #pragma unroll
            for (int i = 0; i < 4; i++)
                #pragma unroll
                for (int j = 0; j < 4; j++)
                    Sa[i][j] = fmaf(qv[i], kv[j], Sa[i][j]);
        }
        #pragma unroll
        for (int i = 0; i < 4; i++)
            #pragma unroll
            for (int j = 0; j < 4; j++)
                Ss[(ty * 4 + i) * 65 + tx * 4 + j] = Sa[i][j];
        __syncthreads();

        // Online softmax row update (threads 0..63, one row each)
        if (tid < 64) {
            float m_old = m_s[tid], l = l_s[tid];
            float mx = m_old;
            #pragma unroll 8
            for (int c = 0; c < 64; c++) mx = fmaxf(mx, Ss[tid * 65 + c]);
            float sum = 0.f;
            #pragma unroll 8
            for (int c = 0; c < 64; c++) {
                float p = __expf(Ss[tid * 65 + c] - mx);
                Ss[tid * 65 + c] = p;
                sum += p;
            }
            float alpha = __expf(m_old - mx);
            l_s[tid] = l * alpha + sum;
            m_s[tid] = mx;
            alpha_s[tid] = alpha;
        }
        __syncthreads();

        // O = O*alpha + P @ V
        float al[4];
        #pragma unroll
        for (int i = 0; i < 4; i++) al[i] = alpha_s[ty * 4 + i];
        #pragma unroll
        for (int i = 0; i < 4; i++)
            #pragma unroll
            for (int j = 0; j < 4; j++) Oa[i][j] *= al[i];

        #pragma unroll 8
        for (int j = 0; j < 64; j++) {
            float p[4], v[4];
            #pragma unroll
            for (int i = 0; i < 4; i++) p[i] = Ss[(ty * 4 + i) * 65 + j];
            #pragma unroll
            for (int c = 0; c < 4; c++) v[c] = Vs[j * 65 + tx * 4 + c];
            #pragma unroll
            for (int i = 0; i < 4; i++)
                #pragma unroll
                for (int c = 0; c < 4; c++)
                    Oa[i][c] = fmaf(p[i], v[c], Oa[i][c]);
        }
    }
    __syncthreads();

    float invl[4];
    #pragma unroll
    for (int i = 0; i < 4; i++) invl[i] = 1.0f / l_s[ty * 4 + i];
    #pragma unroll
    for (int i = 0; i < 4; i++) {
        int tok = q_tok0 + ty * 4 + i;
        #pragma unroll
        for (int c = 0; c < 4; c++)
            o[(size_t)tok * DIM + h * HD + tx * 4 + c] = Oa[i][c] * invl[i];
    }
}

// ---------------------------------------------------------------------------
// Launch
// ---------------------------------------------------------------------------
extern "C" void kernel_launch(void* const* d_in, const int* in_sizes, int n_in,
                              void* d_out, int out_size)
{
    const float* x      = (const float*)d_in[0];
    const float* ln1_g  = (const float*)d_in[1];
    const float* ln1_b  = (const float*)d_in[2];
    const float* w_qkv  = (const float*)d_in[3];
    const float* w_proj = (const float*)d_in[4];
    const float* b_proj = (const float*)d_in[5];
    const float* ln2_g  = (const float*)d_in[6];
    const float* ln2_b  = (const float*)d_in[7];
    const float* w_fc1  = (const float*)d_in[8];
    const float* b_fc1  = (const float*)d_in[9];
    const float* w_fc2  = (const float*)d_in[10];
    const float* b_fc2  = (const float*)d_in[11];
    float* out = (float*)d_out;

    float *p_h, *p_qkv, *p_o, *p_x1, *p_h2, *p_m;
    cudaGetSymbolAddress((void**)&p_h,   g_h);
    cudaGetSymbolAddress((void**)&p_qkv, g_qkv);
    cudaGetSymbolAddress((void**)&p_o,   g_o);
    cudaGetSymbolAddress((void**)&p_x1,  g_x1);
    cudaGetSymbolAddress((void**)&p_h2,  g_h2);
    cudaGetSymbolAddress((void**)&p_m,   g_m);

    const int attn_smem = (4 * 64 * 65 + 3 * 64) * (int)sizeof(float); // 67328 B
    cudaFuncSetAttribute(attn_kernel,
                         cudaFuncAttributeMaxDynamicSharedMemorySize, attn_smem);

    // 1. LN1
    ln_kernel<<<TOK, 256>>>(x, ln1_g, ln1_b, p_h);
    // 2. QKV GEMM: [4096,768] @ [768,2304]
    gemm_kernel<0><<<dim3(H3 / 128, TOK / 128), 256>>>(
        p_h, w_qkv, nullptr, nullptr, p_qkv, TOK, H3, DIM);
    // 3. Attention
    attn_kernel<<<dim3(NSEQ / 64, NHEAD, 2), 256, attn_smem>>>(p_qkv, p_o);
    // 4. Proj GEMM + bias + residual(x)
    gemm_kernel<1><<<dim3(DIM / 128, TOK / 128), 256>>>(
        p_o, w_proj, b_proj, x, p_x1, TOK, DIM, DIM);
    // 5. LN2
    ln_kernel<<<TOK, 256>>>(p_x1, ln2_g, ln2_b, p_h2);
    // 6. FC1 GEMM + bias + GELU
    gemm_kernel<2><<<dim3(HID / 128, TOK / 128), 256>>>(
        p_h2, w_fc1, b_fc1, nullptr, p_m, TOK, HID, DIM);
    // 7. FC2 GEMM + bias + residual(x1) -> d_out
    gemm_kernel<1><<<dim3(DIM / 128, TOK / 128), 256>>>(
        p_m, w_fc2, b_fc2, p_x1, out, TOK, DIM, HID);
}

// round 2
// speedup vs baseline: 1.8793x; 1.8793x over previous
#include <cuda_runtime.h>
#include <math.h>
#include <stdint.h>

// Problem constants
#define TOK   4096      // 2 * 2048 tokens
#define NSEQ  2048
#define DIM   768
#define H3    2304      // 3*DIM
#define HID   3072
#define NHEAD 12
#define HD    64

// Scratch (no allocations allowed -> __device__ globals). 16B+ aligned for cp.async.
__device__ __align__(128) float g_h  [TOK * DIM];   // LN1 out
__device__ __align__(128) float g_qkv[TOK * H3];    // qkv
__device__ __align__(128) float g_o  [TOK * DIM];   // attention out
__device__ __align__(128) float g_x1 [TOK * DIM];   // x + proj
__device__ __align__(128) float g_h2 [TOK * DIM];   // LN2 out
__device__ __align__(128) float g_m  [TOK * HID];   // gelu(fc1)

// ---------------------------------------------------------------------------
// PTX helpers
// ---------------------------------------------------------------------------
__device__ __forceinline__ uint32_t f2tf32(float f) {
    uint32_t u;
    asm("cvt.rna.tf32.f32 %0, %1;" : "=r"(u) : "f"(f));
    return u;
}

__device__ __forceinline__ void mma_tf32(float* d,
    uint32_t a0, uint32_t a1, uint32_t a2, uint32_t a3,
    uint32_t b0, uint32_t b1)
{
    asm volatile(
        "mma.sync.aligned.m16n8k8.row.col.f32.tf32.tf32.f32 "
        "{%0,%1,%2,%3}, {%4,%5,%6,%7}, {%8,%9}, {%0,%1,%2,%3};"
        : "+f"(d[0]), "+f"(d[1]), "+f"(d[2]), "+f"(d[3])
        : "r"(a0), "r"(a1), "r"(a2), "r"(a3), "r"(b0), "r"(b1));
}

__device__ __forceinline__ void cp_async16(uint32_t s, const void* g) {
    asm volatile("cp.async.cg.shared.global [%0], [%1], 16;" :: "r"(s), "l"(g));
}
__device__ __forceinline__ void cp_commit() {
    asm volatile("cp.async.commit_group;" ::);
}
__device__ __forceinline__ void cp_wait0() {
    asm volatile("cp.async.wait_group 0;" ::);
}

// ---------------------------------------------------------------------------
// LayerNorm: one block per row of 768, 256 threads (3 elems/thread)
// ---------------------------------------------------------------------------
__global__ __launch_bounds__(256) void ln_kernel(
    const float* __restrict__ x, const float* __restrict__ g,
    const float* __restrict__ b, float* __restrict__ out)
{
    int row = blockIdx.x;
    int t   = threadIdx.x;
    const float* xr = x + row * DIM;

    float v0 = xr[t], v1 = xr[t + 256], v2 = xr[t + 512];
    float s = v0 + v1 + v2;
    float q = v0 * v0 + v1 * v1 + v2 * v2;

    __shared__ float rs[8], rq[8];
    #pragma unroll
    for (int o = 16; o; o >>= 1) {
        s += __shfl_xor_sync(0xffffffffu, s, o);
        q += __shfl_xor_sync(0xffffffffu, q, o);
    }
    if ((t & 31) == 0) { rs[t >> 5] = s; rq[t >> 5] = q; }
    __syncthreads();

    __shared__ float smu, srstd;
    if (t == 0) {
        float S = 0.f, Q = 0.f;
        #pragma unroll
        for (int i = 0; i < 8; i++) { S += rs[i]; Q += rq[i]; }
        float mu  = S * (1.0f / DIM);
        float var = Q * (1.0f / DIM) - mu * mu;
        smu = mu;
        srstd = rsqrtf(var + 1e-5f);
    }
    __syncthreads();
    float mu = smu, r = srstd;
    float* orow = out + row * DIM;
    orow[t]       = (v0 - mu) * r * g[t]       + b[t];
    orow[t + 256] = (v1 - mu) * r * g[t + 256] + b[t + 256];
    orow[t + 512] = (v2 - mu) * r * g[t + 512] + b[t + 512];
}

// ---------------------------------------------------------------------------
// TF32 tensor-core GEMM: C[M,N] = A[M,K] @ B[K,N] (+ bias/residual/gelu)
// Block tile 128x128, BK=16, 256 threads = 8 warps in 2(m) x 4(n).
// Warp tile 64x32 -> 4 m-frags x 4 n-frags of m16n8k8.
// Double-buffered smem fed by cp.async.
// EPI: 0 = none, 1 = bias + residual, 2 = bias + exact GELU
// ---------------------------------------------------------------------------
#define AS_STRIDE 20    // 16 + 4 pad floats (80B rows, keeps 16B alignment)
#define BS_STRIDE 132   // 128 + 4 pad floats (528B rows)

template<int EPI>
__global__ __launch_bounds__(256) void gemm_tc(
    const float* __restrict__ A, const float* __restrict__ B,
    const float* __restrict__ bias, const float* __restrict__ res,
    float* __restrict__ C, int M, int N, int K)
{
    __shared__ float As[2][128 * AS_STRIDE];
    __shared__ float Bs[2][16 * BS_STRIDE];

    int tid  = threadIdx.x;
    int lane = tid & 31;
    int warp = tid >> 5;
    int wm = warp >> 2;       // 0..1
    int wn = warp & 3;        // 0..3
    int row0 = blockIdx.y * 128;
    int col0 = blockIdx.x * 128;

    float acc[4][4][4];
    #pragma unroll
    for (int mi = 0; mi < 4; mi++)
        #pragma unroll
        for (int ni = 0; ni < 4; ni++)
            #pragma unroll
            for (int j = 0; j < 4; j++) acc[mi][ni][j] = 0.f;

    int gq = lane >> 2;       // groupID   (0..7)
    int gt = lane & 3;        // thread-in-group (0..3)

    // --- async tile loader ---
    auto load_tile = [&](int k0, int buf) {
        // A: 128 rows x 16 cols = 512 x 16B chunks, 2 per thread
        #pragma unroll
        for (int i = 0; i < 2; i++) {
            int e = tid + i * 256;
            int r = e >> 2, c4 = e & 3;
            uint32_t s = (uint32_t)__cvta_generic_to_shared(
                &As[buf][r * AS_STRIDE + c4 * 4]);
            cp_async16(s, A + (size_t)(row0 + r) * K + k0 + c4 * 4);
        }
        // B: 16 rows x 128 cols = 512 x 16B chunks, 2 per thread
        #pragma unroll
        for (int i = 0; i < 2; i++) {
            int e = tid + i * 256;
            int r = e >> 5, c4 = e & 31;
            uint32_t s = (uint32_t)__cvta_generic_to_shared(
                &Bs[buf][r * BS_STRIDE + c4 * 4]);
            cp_async16(s, B + (size_t)(k0 + r) * N + col0 + c4 * 4);
        }
        cp_commit();
    };

    load_tile(0, 0);
    int ntiles = K / 16;

    for (int t = 0; t < ntiles; t++) {
        cp_wait0();
        __syncthreads();                 // all warps done with buf^1 compute + tile t landed
        if (t + 1 < ntiles) load_tile((t + 1) * 16, (t + 1) & 1);
        int buf = t & 1;

        #pragma unroll
        for (int ks = 0; ks < 2; ks++) {
            int kb = ks * 8;
            uint32_t af[4][4];
            #pragma unroll
            for (int mi = 0; mi < 4; mi++) {
                int r = wm * 64 + mi * 16 + gq;
                af[mi][0] = f2tf32(As[buf][ r      * AS_STRIDE + kb + gt    ]);
                af[mi][1] = f2tf32(As[buf][(r + 8) * AS_STRIDE + kb + gt    ]);
                af[mi][2] = f2tf32(As[buf][ r      * AS_STRIDE + kb + gt + 4]);
                af[mi][3] = f2tf32(As[buf][(r + 8) * AS_STRIDE + kb + gt + 4]);
            }
            uint32_t bf[4][2];
            #pragma unroll
            for (int ni = 0; ni < 4; ni++) {
                int c = wn * 32 + ni * 8 + gq;
                bf[ni][0] = f2tf32(Bs[buf][(kb + gt    ) * BS_STRIDE + c]);
                bf[ni][1] = f2tf32(Bs[buf][(kb + gt + 4) * BS_STRIDE + c]);
            }
            #pragma unroll
            for (int mi = 0; mi < 4; mi++)
                #pragma unroll
                for (int ni = 0; ni < 4; ni++)
                    mma_tf32(acc[mi][ni],
                             af[mi][0], af[mi][1], af[mi][2], af[mi][3],
                             bf[ni][0], bf[ni][1]);
        }
    }

    // Epilogue: c0,c1 at (r, c..c+1); c2,c3 at (r+8, c..c+1)
    #pragma unroll
    for (int mi = 0; mi < 4; mi++) {
        int r = row0 + wm * 64 + mi * 16 + gq;
        #pragma unroll
        for (int ni = 0; ni < 4; ni++) {
            int c = col0 + wn * 32 + ni * 8 + gt * 2;
            float v0 = acc[mi][ni][0], v1 = acc[mi][ni][1];
            float v2 = acc[mi][ni][2], v3 = acc[mi][ni][3];
            if (EPI >= 1) {
                float b0 = bias[c], b1 = bias[c + 1];
                v0 += b0; v1 += b1; v2 += b0; v3 += b1;
            }
            if (EPI == 1) {
                const float2 r01 = *(const float2*)&res[(size_t) r      * N + c];
                const float2 r23 = *(const float2*)&res[(size_t)(r + 8) * N + c];
                v0 += r01.x; v1 += r01.y; v2 += r23.x; v3 += r23.y;
            }
            if (EPI == 2) {
                v0 = 0.5f * v0 * (1.0f + erff(v0 * 0.70710678118f));
                v1 = 0.5f * v1 * (1.0f + erff(v1 * 0.70710678118f));
                v2 = 0.5f * v2 * (1.0f + erff(v2 * 0.70710678118f));
                v3 = 0.5f * v3 * (1.0f + erff(v3 * 0.70710678118f));
            }
            *(float2*)&C[(size_t) r      * N + c] = make_float2(v0, v1);
            *(float2*)&C[(size_t)(r + 8) * N + c] = make_float2(v2, v3);
        }
    }
}

// ---------------------------------------------------------------------------
// Flash attention (fp32, online softmax). Unchanged from R0.
// Grid: (32 q-tiles, 12 heads, 2 batch). 256 threads.
// ---------------------------------------------------------------------------
__global__ __launch_bounds__(256) void attn_kernel(
    const float* __restrict__ qkv, float* __restrict__ o)
{
    extern __shared__ float smem[];
    float* Qs      = smem;                 // [64][65]
    float* KsT     = Qs  + 64 * 65;        // [d][n]
    float* Vs      = KsT + 64 * 65;        // [n][d]
    float* Ss      = Vs  + 64 * 65;        // [64][65]
    float* alpha_s = Ss  + 64 * 65;        // [64]
    float* m_s     = alpha_s + 64;         // [64]
    float* l_s     = m_s + 64;             // [64]

    int tid = threadIdx.x;
    int tx  = tid & 15;
    int ty  = tid >> 4;

    int qt = blockIdx.x, h = blockIdx.y, b = blockIdx.z;
    int q_tok0 = b * NSEQ + qt * 64;
    int qcol = h * HD;
    int kcol = DIM + h * HD;
    int vcol = 2 * DIM + h * HD;
    const float scale = 0.125f;

    #pragma unroll
    for (int i = 0; i < 16; i++) {
        int e = tid + i * 256;
        int r = e >> 6, c = e & 63;
        Qs[r * 65 + c] = qkv[(size_t)(q_tok0 + r) * H3 + qcol + c] * scale;
    }
    if (tid < 64) { m_s[tid] = -1e30f; l_s[tid] = 0.f; }

    float Oa[4][4];
    #pragma unroll
    for (int i = 0; i < 4; i++)
        #pragma unroll
        for (int j = 0; j < 4; j++) Oa[i][j] = 0.f;

    for (int kt = 0; kt < NSEQ / 64; kt++) {
        int k_tok0 = b * NSEQ + kt * 64;
        __syncthreads();
        #pragma unroll
        for (int i = 0; i < 16; i++) {
            int e = tid + i * 256;
            int r = e >> 6, c = e & 63;
            KsT[c * 65 + r] = qkv[(size_t)(k_tok0 + r) * H3 + kcol + c];
            Vs [r * 65 + c] = qkv[(size_t)(k_tok0 + r) * H3 + vcol + c];
        }
        __syncthreads();

        float Sa[4][4];
        #pragma unroll
        for (int i = 0; i < 4; i++)
            #pragma unroll
            for (int j = 0; j < 4; j++) Sa[i][j] = 0.f;

        #pragma unroll 8
        for (int d = 0; d < 64; d++) {
            float qv[4], kv[4];
            #pragma unroll
            for (int i = 0; i < 4; i++) qv[i] = Qs[(ty * 4 + i) * 65 + d];
            #pragma unroll
            for (int j = 0; j < 4; j++) kv[j] = KsT[d * 65 + tx * 4 + j];
            #pragma unroll
            for (int i = 0; i < 4; i++)
                #pragma unroll
                for (int j = 0; j < 4; j++)
                    Sa[i][j] = fmaf(qv[i], kv[j], Sa[i][j]);
        }
        #pragma unroll
        for (int i = 0; i < 4; i++)
            #pragma unroll
            for (int j = 0; j < 4; j++)
                Ss[(ty * 4 + i) * 65 + tx * 4 + j] = Sa[i][j];
        __syncthreads();

        if (tid < 64) {
            float m_old = m_s[tid], l = l_s[tid];
            float mx = m_old;
            #pragma unroll 8
            for (int c = 0; c < 64; c++) mx = fmaxf(mx, Ss[tid * 65 + c]);
            float sum = 0.f;
            #pragma unroll 8
            for (int c = 0; c < 64; c++) {
                float p = __expf(Ss[tid * 65 + c] - mx);
                Ss[tid * 65 + c] = p;
                sum += p;
            }
            float alpha = __expf(m_old - mx);
            l_s[tid] = l * alpha + sum;
            m_s[tid] = mx;
            alpha_s[tid] = alpha;
        }
        __syncthreads();

        float al[4];
        #pragma unroll
        for (int i = 0; i < 4; i++) al[i] = alpha_s[ty * 4 + i];
        #pragma unroll
        for (int i = 0; i < 4; i++)
            #pragma unroll
            for (int j = 0; j < 4; j++) Oa[i][j] *= al[i];

        #pragma unroll 8
        for (int j = 0; j < 64; j++) {
            float p[4], v[4];
            #pragma unroll
            for (int i = 0; i < 4; i++) p[i] = Ss[(ty * 4 + i) * 65 + j];
            #pragma unroll
            for (int c = 0; c < 4; c++) v[c] = Vs[j * 65 + tx * 4 + c];
            #pragma unroll
            for (int i = 0; i < 4; i++)
                #pragma unroll
                for (int c = 0; c < 4; c++)
                    Oa[i][c] = fmaf(p[i], v[c], Oa[i][c]);
        }
    }
    __syncthreads();

    float invl[4];
    #pragma unroll
    for (int i = 0; i < 4; i++) invl[i] = 1.0f / l_s[ty * 4 + i];
    #pragma unroll
    for (int i = 0; i < 4; i++) {
        int tok = q_tok0 + ty * 4 + i;
        #pragma unroll
        for (int c = 0; c < 4; c++)
            o[(size_t)tok * DIM + h * HD + tx * 4 + c] = Oa[i][c] * invl[i];
    }
}

// ---------------------------------------------------------------------------
// Launch
// ---------------------------------------------------------------------------
extern "C" void kernel_launch(void* const* d_in, const int* in_sizes, int n_in,
                              void* d_out, int out_size)
{
    const float* x      = (const float*)d_in[0];
    const float* ln1_g  = (const float*)d_in[1];
    const float* ln1_b  = (const float*)d_in[2];
    const float* w_qkv  = (const float*)d_in[3];
    const float* w_proj = (const float*)d_in[4];
    const float* b_proj = (const float*)d_in[5];
    const float* ln2_g  = (const float*)d_in[6];
    const float* ln2_b  = (const float*)d_in[7];
    const float* w_fc1  = (const float*)d_in[8];
    const float* b_fc1  = (const float*)d_in[9];
    const float* w_fc2  = (const float*)d_in[10];
    const float* b_fc2  = (const float*)d_in[11];
    float* out = (float*)d_out;

    float *p_h, *p_qkv, *p_o, *p_x1, *p_h2, *p_m;
    cudaGetSymbolAddress((void**)&p_h,   g_h);
    cudaGetSymbolAddress((void**)&p_qkv, g_qkv);
    cudaGetSymbolAddress((void**)&p_o,   g_o);
    cudaGetSymbolAddress((void**)&p_x1,  g_x1);
    cudaGetSymbolAddress((void**)&p_h2,  g_h2);
    cudaGetSymbolAddress((void**)&p_m,   g_m);

    const int attn_smem = (4 * 64 * 65 + 3 * 64) * (int)sizeof(float); // 67328 B
    cudaFuncSetAttribute(attn_kernel,
                         cudaFuncAttributeMaxDynamicSharedMemorySize, attn_smem);

    // 1. LN1
    ln_kernel<<<TOK, 256>>>(x, ln1_g, ln1_b, p_h);
    // 2. QKV GEMM: [4096,768] @ [768,2304]
    gemm_tc<0><<<dim3(H3 / 128, TOK / 128), 256>>>(
        p_h, w_qkv, nullptr, nullptr, p_qkv, TOK, H3, DIM);
    // 3. Attention
    attn_kernel<<<dim3(NSEQ / 64, NHEAD, 2), 256, attn_smem>>>(p_qkv, p_o);
    // 4. Proj GEMM + bias + residual(x)
    gemm_tc<1><<<dim3(DIM / 128, TOK / 128), 256>>>(
        p_o, w_proj, b_proj, x, p_x1, TOK, DIM, DIM);
    // 5. LN2
    ln_kernel<<<TOK, 256>>>(p_x1, ln2_g, ln2_b, p_h2);
    // 6. FC1 GEMM + bias + GELU
    gemm_tc<2><<<dim3(HID / 128, TOK / 128), 256>>>(
        p_h2, w_fc1, b_fc1, nullptr, p_m, TOK, HID, DIM);
    // 7. FC2 GEMM + bias + residual(x1) -> d_out
    gemm_tc<1><<<dim3(DIM / 128, TOK / 128), 256>>>(
        p_m, w_fc2, b_fc2, p_x1, out, TOK, DIM, HID);
}

// round 3
// speedup vs baseline: 3.0076x; 1.6004x over previous
#include <cuda_runtime.h>
#include <math.h>
#include <stdint.h>

// Problem constants
#define TOK   4096      // 2 * 2048 tokens
#define NSEQ  2048
#define DIM   768
#define H3    2304      // 3*DIM
#define HID   3072
#define NHEAD 12
#define HD    64

// Scratch (no allocations allowed -> __device__ globals). 16B+ aligned for cp.async.
__device__ __align__(128) float g_h  [TOK * DIM];   // LN1 out
__device__ __align__(128) float g_qkv[TOK * H3];    // qkv
__device__ __align__(128) float g_o  [TOK * DIM];   // attention out
__device__ __align__(128) float g_x1 [TOK * DIM];   // x + proj
__device__ __align__(128) float g_h2 [TOK * DIM];   // LN2 out
__device__ __align__(128) float g_m  [TOK * HID];   // gelu(fc1)

// ---------------------------------------------------------------------------
// PTX helpers
// ---------------------------------------------------------------------------
__device__ __forceinline__ uint32_t f2tf32(float f) {
    uint32_t u;
    asm("cvt.rna.tf32.f32 %0, %1;" : "=r"(u) : "f"(f));
    return u;
}

__device__ __forceinline__ void mma_tf32(float* d,
    uint32_t a0, uint32_t a1, uint32_t a2, uint32_t a3,
    uint32_t b0, uint32_t b1)
{
    asm volatile(
        "mma.sync.aligned.m16n8k8.row.col.f32.tf32.tf32.f32 "
        "{%0,%1,%2,%3}, {%4,%5,%6,%7}, {%8,%9}, {%0,%1,%2,%3};"
        : "+f"(d[0]), "+f"(d[1]), "+f"(d[2]), "+f"(d[3])
        : "r"(a0), "r"(a1), "r"(a2), "r"(a3), "r"(b0), "r"(b1));
}

__device__ __forceinline__ void cp_async16(uint32_t s, const void* g) {
    asm volatile("cp.async.cg.shared.global [%0], [%1], 16;" :: "r"(s), "l"(g));
}
__device__ __forceinline__ void cp_commit() {
    asm volatile("cp.async.commit_group;" ::);
}
__device__ __forceinline__ void cp_wait0() {
    asm volatile("cp.async.wait_group 0;" ::);
}

// ---------------------------------------------------------------------------
// LayerNorm: one block per row of 768, 256 threads (3 elems/thread)
// ---------------------------------------------------------------------------
__global__ __launch_bounds__(256) void ln_kernel(
    const float* __restrict__ x, const float* __restrict__ g,
    const float* __restrict__ b, float* __restrict__ out)
{
    int row = blockIdx.x;
    int t   = threadIdx.x;
    const float* xr = x + row * DIM;

    float v0 = xr[t], v1 = xr[t + 256], v2 = xr[t + 512];
    float s = v0 + v1 + v2;
    float q = v0 * v0 + v1 * v1 + v2 * v2;

    __shared__ float rs[8], rq[8];
    #pragma unroll
    for (int o = 16; o; o >>= 1) {
        s += __shfl_xor_sync(0xffffffffu, s, o);
        q += __shfl_xor_sync(0xffffffffu, q, o);
    }
    if ((t & 31) == 0) { rs[t >> 5] = s; rq[t >> 5] = q; }
    __syncthreads();

    __shared__ float smu, srstd;
    if (t == 0) {
        float S = 0.f, Q = 0.f;
        #pragma unroll
        for (int i = 0; i < 8; i++) { S += rs[i]; Q += rq[i]; }
        float mu  = S * (1.0f / DIM);
        float var = Q * (1.0f / DIM) - mu * mu;
        smu = mu;
        srstd = rsqrtf(var + 1e-5f);
    }
    __syncthreads();
    float mu = smu, r = srstd;
    float* orow = out + row * DIM;
    orow[t]       = (v0 - mu) * r * g[t]       + b[t];
    orow[t + 256] = (v1 - mu) * r * g[t + 256] + b[t + 256];
    orow[t + 512] = (v2 - mu) * r * g[t + 512] + b[t + 512];
}

// ---------------------------------------------------------------------------
// TF32 tensor-core GEMM: C[M,N] = A[M,K] @ B[K,N] (+ bias/residual/gelu)
// Block tile 128x128, BK=16, 256 threads = 8 warps in 2(m) x 4(n).
// EPI: 0 = none, 1 = bias + residual, 2 = bias + exact GELU
// ---------------------------------------------------------------------------
#define AS_STRIDE 20    // 16 + 4 pad floats
#define BS_STRIDE 132   // 128 + 4 pad floats

template<int EPI>
__global__ __launch_bounds__(256) void gemm_tc(
    const float* __restrict__ A, const float* __restrict__ B,
    const float* __restrict__ bias, const float* __restrict__ res,
    float* __restrict__ C, int M, int N, int K)
{
    __shared__ float As[2][128 * AS_STRIDE];
    __shared__ float Bs[2][16 * BS_STRIDE];

    int tid  = threadIdx.x;
    int lane = tid & 31;
    int warp = tid >> 5;
    int wm = warp >> 2;       // 0..1
    int wn = warp & 3;        // 0..3
    int row0 = blockIdx.y * 128;
    int col0 = blockIdx.x * 128;

    float acc[4][4][4];
    #pragma unroll
    for (int mi = 0; mi < 4; mi++)
        #pragma unroll
        for (int ni = 0; ni < 4; ni++)
            #pragma unroll
            for (int j = 0; j < 4; j++) acc[mi][ni][j] = 0.f;

    int gq = lane >> 2;
    int gt = lane & 3;

    auto load_tile = [&](int k0, int buf) {
        #pragma unroll
        for (int i = 0; i < 2; i++) {
            int e = tid + i * 256;
            int r = e >> 2, c4 = e & 3;
            uint32_t s = (uint32_t)__cvta_generic_to_shared(
                &As[buf][r * AS_STRIDE + c4 * 4]);
            cp_async16(s, A + (size_t)(row0 + r) * K + k0 + c4 * 4);
        }
        #pragma unroll
        for (int i = 0; i < 2; i++) {
            int e = tid + i * 256;
            int r = e >> 5, c4 = e & 31;
            uint32_t s = (uint32_t)__cvta_generic_to_shared(
                &Bs[buf][r * BS_STRIDE + c4 * 4]);
            cp_async16(s, B + (size_t)(k0 + r) * N + col0 + c4 * 4);
        }
        cp_commit();
    };

    load_tile(0, 0);
    int ntiles = K / 16;

    for (int t = 0; t < ntiles; t++) {
        cp_wait0();
        __syncthreads();
        if (t + 1 < ntiles) load_tile((t + 1) * 16, (t + 1) & 1);
        int buf = t & 1;

        #pragma unroll
        for (int ks = 0; ks < 2; ks++) {
            int kb = ks * 8;
            uint32_t af[4][4];
            #pragma unroll
            for (int mi = 0; mi < 4; mi++) {
                int r = wm * 64 + mi * 16 + gq;
                af[mi][0] = f2tf32(As[buf][ r      * AS_STRIDE + kb + gt    ]);
                af[mi][1] = f2tf32(As[buf][(r + 8) * AS_STRIDE + kb + gt    ]);
                af[mi][2] = f2tf32(As[buf][ r      * AS_STRIDE + kb + gt + 4]);
                af[mi][3] = f2tf32(As[buf][(r + 8) * AS_STRIDE + kb + gt + 4]);
            }
            uint32_t bf[4][2];
            #pragma unroll
            for (int ni = 0; ni < 4; ni++) {
                int c = wn * 32 + ni * 8 + gq;
                bf[ni][0] = f2tf32(Bs[buf][(kb + gt    ) * BS_STRIDE + c]);
                bf[ni][1] = f2tf32(Bs[buf][(kb + gt + 4) * BS_STRIDE + c]);
            }
            #pragma unroll
            for (int mi = 0; mi < 4; mi++)
                #pragma unroll
                for (int ni = 0; ni < 4; ni++)
                    mma_tf32(acc[mi][ni],
                             af[mi][0], af[mi][1], af[mi][2], af[mi][3],
                             bf[ni][0], bf[ni][1]);
        }
    }

    #pragma unroll
    for (int mi = 0; mi < 4; mi++) {
        int r = row0 + wm * 64 + mi * 16 + gq;
        #pragma unroll
        for (int ni = 0; ni < 4; ni++) {
            int c = col0 + wn * 32 + ni * 8 + gt * 2;
            float v0 = acc[mi][ni][0], v1 = acc[mi][ni][1];
            float v2 = acc[mi][ni][2], v3 = acc[mi][ni][3];
            if (EPI >= 1) {
                float b0 = bias[c], b1 = bias[c + 1];
                v0 += b0; v1 += b1; v2 += b0; v3 += b1;
            }
            if (EPI == 1) {
                const float2 r01 = *(const float2*)&res[(size_t) r      * N + c];
                const float2 r23 = *(const float2*)&res[(size_t)(r + 8) * N + c];
                v0 += r01.x; v1 += r01.y; v2 += r23.x; v3 += r23.y;
            }
            if (EPI == 2) {
                v0 = 0.5f * v0 * (1.0f + erff(v0 * 0.70710678118f));
                v1 = 0.5f * v1 * (1.0f + erff(v1 * 0.70710678118f));
                v2 = 0.5f * v2 * (1.0f + erff(v2 * 0.70710678118f));
                v3 = 0.5f * v3 * (1.0f + erff(v3 * 0.70710678118f));
            }
            *(float2*)&C[(size_t) r      * N + c] = make_float2(v0, v1);
            *(float2*)&C[(size_t)(r + 8) * N + c] = make_float2(v2, v3);
        }
    }
}

// ---------------------------------------------------------------------------
// Tensor-core flash attention (tf32 mma, online softmax in fragments).
// Grid: (32 q-tiles, 12 heads, 2 batch). 128 threads = 4 warps.
// Warp owns 16 q rows. Q frags register-resident, K/V double-buffered cp.async.
// Smem strides: K/Q/P 68 (conflict-free: bank = 4*gq+gt), V 72 (bank = 8*gt+gq).
// ---------------------------------------------------------------------------
#define KST 68
#define VST 72
// layout: QP region [64*KST] (Q staging, later per-warp P tiles), K[2][64*KST], V[2][64*VST]
#define SM_QP 0
#define SM_K  (64 * KST)
#define SM_V  (SM_K + 2 * 64 * KST)
#define ATTN_SMEM_FLOATS (SM_V + 2 * 64 * VST)

__global__ __launch_bounds__(128) void attn_tc(
    const float* __restrict__ qkv, float* __restrict__ o)
{
    extern __shared__ float sm[];
    float* QP = sm + SM_QP;
    float* Ks = sm + SM_K;
    float* Vs = sm + SM_V;

    int tid  = threadIdx.x;
    int lane = tid & 31;
    int warp = tid >> 5;
    int gq   = lane >> 2;   // 0..7
    int gt   = lane & 3;    // 0..3
    int wr   = warp * 16;   // warp's q-row base within the 64-row tile

    int qt = blockIdx.x, h = blockIdx.y, b = blockIdx.z;
    int q_tok0 = b * NSEQ + qt * 64;
    int qcol = h * HD;
    int kcol = DIM + h * HD;
    int vcol = 2 * DIM + h * HD;
    const float scale = 0.125f;  // 1/sqrt(64)

    // --- async loader for one K/V tile (64 tokens x 64 dims each) ---
    auto load_kv = [&](int kt, int buf) {
        int k_tok0 = b * NSEQ + kt * 64;
        #pragma unroll
        for (int i = 0; i < 8; i++) {
            int e = tid + i * 128;
            int r = e >> 4, c4 = e & 15;
            const float* gk = qkv + (size_t)(k_tok0 + r) * H3 + kcol + c4 * 4;
            const float* gv = qkv + (size_t)(k_tok0 + r) * H3 + vcol + c4 * 4;
            cp_async16((uint32_t)__cvta_generic_to_shared(
                &Ks[buf * 64 * KST + r * KST + c4 * 4]), gk);
            cp_async16((uint32_t)__cvta_generic_to_shared(
                &Vs[buf * 64 * VST + r * VST + c4 * 4]), gv);
        }
        cp_commit();
    };

    // Kick off K/V tile 0, then stage Q while it flies.
    load_kv(0, 0);

    #pragma unroll
    for (int i = 0; i < 8; i++) {
        int e = tid + i * 128;
        int r = e >> 4, c4 = e & 15;
        float4 v = *(const float4*)(qkv + (size_t)(q_tok0 + r) * H3 + qcol + c4 * 4);
        v.x *= scale; v.y *= scale; v.z *= scale; v.w *= scale;
        *(float4*)&QP[r * KST + c4 * 4] = v;
    }
    __syncthreads();

    // Q fragments (row-major A for m16n8k8): persistent in registers
    uint32_t qf[8][4];
    #pragma unroll
    for (int ks = 0; ks < 8; ks++) {
        int kb = ks * 8;
        qf[ks][0] = f2tf32(QP[(wr + gq    ) * KST + kb + gt    ]);
        qf[ks][1] = f2tf32(QP[(wr + gq + 8) * KST + kb + gt    ]);
        qf[ks][2] = f2tf32(QP[(wr + gq    ) * KST + kb + gt + 4]);
        qf[ks][3] = f2tf32(QP[(wr + gq + 8) * KST + kb + gt + 4]);
    }
    __syncthreads();   // QP now free for per-warp P tiles

    float* Ps = QP + warp * 16 * KST;   // this warp's 16x64 P staging

    float m0 = -1e30f, m1 = -1e30f, l0 = 0.f, l1 = 0.f;
    float oacc[8][4];
    #pragma unroll
    for (int nf = 0; nf < 8; nf++)
        #pragma unroll
        for (int j = 0; j < 4; j++) oacc[nf][j] = 0.f;

    for (int kt = 0; kt < NSEQ / 64; kt++) {
        cp_wait0();
        __syncthreads();
        if (kt + 1 < NSEQ / 64) load_kv(kt + 1, (kt + 1) & 1);
        const float* Kb = Ks + (kt & 1) * 64 * KST;
        const float* Vb = Vs + (kt & 1) * 64 * VST;

        // ---- S = Q @ K^T : 8 n-frags (keys) x 8 k-steps (d) ----
        float sacc[8][4];
        #pragma unroll
        for (int nf = 0; nf < 8; nf++)
            #pragma unroll
            for (int j = 0; j < 4; j++) sacc[nf][j] = 0.f;

        #pragma unroll
        for (int ks = 0; ks < 8; ks++) {
            int kb = ks * 8;
            #pragma unroll
            for (int nf = 0; nf < 8; nf++) {
                uint32_t b0 = f2tf32(Kb[(nf * 8 + gq) * KST + kb + gt    ]);
                uint32_t b1 = f2tf32(Kb[(nf * 8 + gq) * KST + kb + gt + 4]);
                mma_tf32(sacc[nf], qf[ks][0], qf[ks][1], qf[ks][2], qf[ks][3], b0, b1);
            }
        }

        // ---- online softmax in fragments ----
        float mx0 = -1e30f, mx1 = -1e30f;
        #pragma unroll
        for (int nf = 0; nf < 8; nf++) {
            mx0 = fmaxf(mx0, fmaxf(sacc[nf][0], sacc[nf][1]));
            mx1 = fmaxf(mx1, fmaxf(sacc[nf][2], sacc[nf][3]));
        }
        mx0 = fmaxf(mx0, __shfl_xor_sync(0xffffffffu, mx0, 1));
        mx0 = fmaxf(mx0, __shfl_xor_sync(0xffffffffu, mx0, 2));
        mx1 = fmaxf(mx1, __shfl_xor_sync(0xffffffffu, mx1, 1));
        mx1 = fmaxf(mx1, __shfl_xor_sync(0xffffffffu, mx1, 2));

        float mn0 = fmaxf(m0, mx0), mn1 = fmaxf(m1, mx1);
        float alpha0 = __expf(m0 - mn0), alpha1 = __expf(m1 - mn1);
        m0 = mn0; m1 = mn1;

        float sum0 = 0.f, sum1 = 0.f;
        #pragma unroll
        for (int nf = 0; nf < 8; nf++) {
            float p0 = __expf(sacc[nf][0] - mn0);
            float p1 = __expf(sacc[nf][1] - mn0);
            float p2 = __expf(sacc[nf][2] - mn1);
            float p3 = __expf(sacc[nf][3] - mn1);
            sum0 += p0 + p1; sum1 += p2 + p3;
            *(float2*)&Ps[ gq      * KST + nf * 8 + gt * 2] = make_float2(p0, p1);
            *(float2*)&Ps[(gq + 8) * KST + nf * 8 + gt * 2] = make_float2(p2, p3);
        }
        sum0 += __shfl_xor_sync(0xffffffffu, sum0, 1);
        sum0 += __shfl_xor_sync(0xffffffffu, sum0, 2);
        sum1 += __shfl_xor_sync(0xffffffffu, sum1, 1);
        sum1 += __shfl_xor_sync(0xffffffffu, sum1, 2);
        l0 = l0 * alpha0 + sum0;
        l1 = l1 * alpha1 + sum1;

        #pragma unroll
        for (int nf = 0; nf < 8; nf++) {
            oacc[nf][0] *= alpha0; oacc[nf][1] *= alpha0;
            oacc[nf][2] *= alpha1; oacc[nf][3] *= alpha1;
        }
        __syncwarp();   // P visible to whole warp

        // ---- O += P @ V : k-dim = keys (64), n-frags = head dims ----
        #pragma unroll
        for (int ks = 0; ks < 8; ks++) {
            int kb = ks * 8;
            uint32_t a0 = f2tf32(Ps[ gq      * KST + kb + gt    ]);
            uint32_t a1 = f2tf32(Ps[(gq + 8) * KST + kb + gt    ]);
            uint32_t a2 = f2tf32(Ps[ gq      * KST + kb + gt + 4]);
            uint32_t a3 = f2tf32(Ps[(gq + 8) * KST + kb + gt + 4]);
            #pragma unroll
            for (int nf = 0; nf < 8; nf++) {
                uint32_t b0 = f2tf32(Vb[(kb + gt    ) * VST + nf * 8 + gq]);
                uint32_t b1 = f2tf32(Vb[(kb + gt + 4) * VST + nf * 8 + gq]);
                mma_tf32(oacc[nf], a0, a1, a2, a3, b0, b1);
            }
        }
        __syncwarp();   // P reads done before next iteration overwrites
    }

    // ---- write O / l ----
    float invl0 = 1.0f / l0, invl1 = 1.0f / l1;
    int r0 = q_tok0 + wr + gq;
    #pragma unroll
    for (int nf = 0; nf < 8; nf++) {
        int c = h * HD + nf * 8 + gt * 2;
        *(float2*)&o[(size_t) r0      * DIM + c] =
            make_float2(oacc[nf][0] * invl0, oacc[nf][1] * invl0);
        *(float2*)&o[(size_t)(r0 + 8) * DIM + c] =
            make_float2(oacc[nf][2] * invl1, oacc[nf][3] * invl1);
    }
}

// ---------------------------------------------------------------------------
// Launch
// ---------------------------------------------------------------------------
extern "C" void kernel_launch(void* const* d_in, const int* in_sizes, int n_in,
                              void* d_out, int out_size)
{
    const float* x      = (const float*)d_in[0];
    const float* ln1_g  = (const float*)d_in[1];
    const float* ln1_b  = (const float*)d_in[2];
    const float* w_qkv  = (const float*)d_in[3];
    const float* w_proj = (const float*)d_in[4];
    const float* b_proj = (const float*)d_in[5];
    const float* ln2_g  = (const float*)d_in[6];
    const float* ln2_b  = (const float*)d_in[7];
    const float* w_fc1  = (const float*)d_in[8];
    const float* b_fc1  = (const float*)d_in[9];
    const float* w_fc2  = (const float*)d_in[10];
    const float* b_fc2  = (const float*)d_in[11];
    float* out = (float*)d_out;

    float *p_h, *p_qkv, *p_o, *p_x1, *p_h2, *p_m;
    cudaGetSymbolAddress((void**)&p_h,   g_h);
    cudaGetSymbolAddress((void**)&p_qkv, g_qkv);
    cudaGetSymbolAddress((void**)&p_o,   g_o);
    cudaGetSymbolAddress((void**)&p_x1,  g_x1);
    cudaGetSymbolAddress((void**)&p_h2,  g_h2);
    cudaGetSymbolAddress((void**)&p_m,   g_m);

    const int attn_smem = ATTN_SMEM_FLOATS * (int)sizeof(float); // ~87 KB
    cudaFuncSetAttribute(attn_tc,
                         cudaFuncAttributeMaxDynamicSharedMemorySize, attn_smem);

    // 1. LN1
    ln_kernel<<<TOK, 256>>>(x, ln1_g, ln1_b, p_h);
    // 2. QKV GEMM: [4096,768] @ [768,2304]
    gemm_tc<0><<<dim3(H3 / 128, TOK / 128), 256>>>(
        p_h, w_qkv, nullptr, nullptr, p_qkv, TOK, H3, DIM);
    // 3. Attention (tensor cores)
    attn_tc<<<dim3(NSEQ / 64, NHEAD, 2), 128, attn_smem>>>(p_qkv, p_o);
    // 4. Proj GEMM + bias + residual(x)
    gemm_tc<1><<<dim3(DIM / 128, TOK / 128), 256>>>(
        p_o, w_proj, b_proj, x, p_x1, TOK, DIM, DIM);
    // 5. LN2
    ln_kernel<<<TOK, 256>>>(p_x1, ln2_g, ln2_b, p_h2);
    // 6. FC1 GEMM + bias + GELU
    gemm_tc<2><<<dim3(HID / 128, TOK / 128), 256>>>(
        p_h2, w_fc1, b_fc1, nullptr, p_m, TOK, HID, DIM);
    // 7. FC2 GEMM + bias + residual(x1) -> d_out
    gemm_tc<1><<<dim3(DIM / 128, TOK / 128), 256>>>(
        p_m, w_fc2, b_fc2, p_x1, out, TOK, DIM, HID);
}

// round 4
// speedup vs baseline: 3.1050x; 1.0324x over previous
#include <cuda_runtime.h>
#include <math.h>
#include <stdint.h>

// Problem constants
#define TOK   4096      // 2 * 2048 tokens
#define NSEQ  2048
#define DIM   768
#define H3    2304      // 3*DIM
#define HID   3072
#define NHEAD 12
#define HD    64

// Scratch (no allocations allowed -> __device__ globals). 16B+ aligned for cp.async.
__device__ __align__(128) float g_h  [TOK * DIM];   // LN1 out (tf32-rounded)
__device__ __align__(128) float g_qkv[TOK * H3];    // qkv
__device__ __align__(128) float g_o  [TOK * DIM];   // attention out (tf32-rounded)
__device__ __align__(128) float g_x1 [TOK * DIM];   // x + proj (full fp32)
__device__ __align__(128) float g_h2 [TOK * DIM];   // LN2 out (tf32-rounded)
__device__ __align__(128) float g_m  [TOK * HID];   // gelu(fc1) (tf32-rounded)
// tf32-rounded weight copies
__device__ __align__(128) float g_wq [DIM * H3];
__device__ __align__(128) float g_wp [DIM * DIM];
__device__ __align__(128) float g_w1 [DIM * HID];
__device__ __align__(128) float g_w2 [HID * DIM];

// ---------------------------------------------------------------------------
// PTX helpers
// ---------------------------------------------------------------------------
__device__ __forceinline__ uint32_t f2tf32(float f) {
    uint32_t u;
    asm("cvt.rna.tf32.f32 %0, %1;" : "=r"(u) : "f"(f));
    return u;
}
__device__ __forceinline__ float round_tf32(float f) {
    return __uint_as_float(f2tf32(f));
}

__device__ __forceinline__ void mma_tf32(float* d,
    uint32_t a0, uint32_t a1, uint32_t a2, uint32_t a3,
    uint32_t b0, uint32_t b1)
{
    asm volatile(
        "mma.sync.aligned.m16n8k8.row.col.f32.tf32.tf32.f32 "
        "{%0,%1,%2,%3}, {%4,%5,%6,%7}, {%8,%9}, {%0,%1,%2,%3};"
        : "+f"(d[0]), "+f"(d[1]), "+f"(d[2]), "+f"(d[3])
        : "r"(a0), "r"(a1), "r"(a2), "r"(a3), "r"(b0), "r"(b1));
}

__device__ __forceinline__ void cp_async16(uint32_t s, const void* g) {
    asm volatile("cp.async.cg.shared.global [%0], [%1], 16;" :: "r"(s), "l"(g));
}
__device__ __forceinline__ void cp_commit() {
    asm volatile("cp.async.commit_group;" ::);
}
template<int N>
__device__ __forceinline__ void cp_wait() {
    asm volatile("cp.async.wait_group %0;" :: "n"(N));
}

// ---------------------------------------------------------------------------
// Weight pre-rounding to tf32 (once per launch; ~7M elems, ~10us)
// ---------------------------------------------------------------------------
__global__ __launch_bounds__(256) void round_w_kernel(
    const float4* __restrict__ src, float4* __restrict__ dst, int n4)
{
    int i = blockIdx.x * 256 + threadIdx.x;
    if (i < n4) {
        float4 v = src[i];
        v.x = round_tf32(v.x); v.y = round_tf32(v.y);
        v.z = round_tf32(v.z); v.w = round_tf32(v.w);
        dst[i] = v;
    }
}

// ---------------------------------------------------------------------------
// LayerNorm: one block per row of 768, 256 threads. Output tf32-rounded.
// ---------------------------------------------------------------------------
__global__ __launch_bounds__(256) void ln_kernel(
    const float* __restrict__ x, const float* __restrict__ g,
    const float* __restrict__ b, float* __restrict__ out)
{
    int row = blockIdx.x;
    int t   = threadIdx.x;
    const float* xr = x + row * DIM;

    float v0 = xr[t], v1 = xr[t + 256], v2 = xr[t + 512];
    float s = v0 + v1 + v2;
    float q = v0 * v0 + v1 * v1 + v2 * v2;

    __shared__ float rs[8], rq[8];
    #pragma unroll
    for (int o = 16; o; o >>= 1) {
        s += __shfl_xor_sync(0xffffffffu, s, o);
        q += __shfl_xor_sync(0xffffffffu, q, o);
    }
    if ((t & 31) == 0) { rs[t >> 5] = s; rq[t >> 5] = q; }
    __syncthreads();

    __shared__ float smu, srstd;
    if (t == 0) {
        float S = 0.f, Q = 0.f;
        #pragma unroll
        for (int i = 0; i < 8; i++) { S += rs[i]; Q += rq[i]; }
        float mu  = S * (1.0f / DIM);
        float var = Q * (1.0f / DIM) - mu * mu;
        smu = mu;
        srstd = rsqrtf(var + 1e-5f);
    }
    __syncthreads();
    float mu = smu, r = srstd;
    float* orow = out + row * DIM;
    orow[t]       = round_tf32((v0 - mu) * r * g[t]       + b[t]);
    orow[t + 256] = round_tf32((v1 - mu) * r * g[t + 256] + b[t + 256]);
    orow[t + 512] = round_tf32((v2 - mu) * r * g[t + 512] + b[t + 512]);
}

// ---------------------------------------------------------------------------
// TF32 tensor-core GEMM, inputs PRE-ROUNDED to tf32 (no cvt in loop).
// Block tile 128x128, BK=16, 3-stage cp.async pipeline, 256 threads (8 warps).
// EPI: 0 = none, 1 = bias + residual, 2 = bias + exact GELU (tf32-rounded out)
// ---------------------------------------------------------------------------
#define AS_STRIDE 20    // 16 + 4 pad floats
#define BS_STRIDE 132   // 128 + 4 pad floats
#define STAGES 3

template<int EPI>
__global__ __launch_bounds__(256) void gemm_tc(
    const float* __restrict__ A, const float* __restrict__ B,
    const float* __restrict__ bias, const float* __restrict__ res,
    float* __restrict__ C, int M, int N, int K)
{
    __shared__ float As[STAGES][128 * AS_STRIDE];
    __shared__ float Bs[STAGES][16 * BS_STRIDE];

    int tid  = threadIdx.x;
    int lane = tid & 31;
    int warp = tid >> 5;
    int wm = warp >> 2;       // 0..1
    int wn = warp & 3;        // 0..3
    int row0 = blockIdx.y * 128;
    int col0 = blockIdx.x * 128;

    float acc[4][4][4];
    #pragma unroll
    for (int mi = 0; mi < 4; mi++)
        #pragma unroll
        for (int ni = 0; ni < 4; ni++)
            #pragma unroll
            for (int j = 0; j < 4; j++) acc[mi][ni][j] = 0.f;

    int gq = lane >> 2;
    int gt = lane & 3;

    auto load_tile = [&](int k0, int buf) {
        #pragma unroll
        for (int i = 0; i < 2; i++) {
            int e = tid + i * 256;
            int r = e >> 2, c4 = e & 3;
            uint32_t s = (uint32_t)__cvta_generic_to_shared(
                &As[buf][r * AS_STRIDE + c4 * 4]);
            cp_async16(s, A + (size_t)(row0 + r) * K + k0 + c4 * 4);
        }
        #pragma unroll
        for (int i = 0; i < 2; i++) {
            int e = tid + i * 256;
            int r = e >> 5, c4 = e & 31;
            uint32_t s = (uint32_t)__cvta_generic_to_shared(
                &Bs[buf][r * BS_STRIDE + c4 * 4]);
            cp_async16(s, B + (size_t)(k0 + r) * N + col0 + c4 * 4);
        }
        cp_commit();
    };

    int ntiles = K / 16;   // >= 48 for this problem
    load_tile(0, 0);
    load_tile(16, 1);

    for (int t = 0; t < ntiles; t++) {
        cp_wait<STAGES - 2>();      // tile t landed
        __syncthreads();            // all warps done reading buf (t-1)%S
        if (t + 2 < ntiles) load_tile((t + 2) * 16, (t + 2) % STAGES);
        int buf = t % STAGES;

        const uint32_t* Au = (const uint32_t*)As[buf];
        const uint32_t* Bu = (const uint32_t*)Bs[buf];

        #pragma unroll
        for (int ks = 0; ks < 2; ks++) {
            int kb = ks * 8;
            uint32_t af[4][4];
            #pragma unroll
            for (int mi = 0; mi < 4; mi++) {
                int r = wm * 64 + mi * 16 + gq;
                af[mi][0] = Au[ r      * AS_STRIDE + kb + gt    ];
                af[mi][1] = Au[(r + 8) * AS_STRIDE + kb + gt    ];
                af[mi][2] = Au[ r      * AS_STRIDE + kb + gt + 4];
                af[mi][3] = Au[(r + 8) * AS_STRIDE + kb + gt + 4];
            }
            uint32_t bf[4][2];
            #pragma unroll
            for (int ni = 0; ni < 4; ni++) {
                int c = wn * 32 + ni * 8 + gq;
                bf[ni][0] = Bu[(kb + gt    ) * BS_STRIDE + c];
                bf[ni][1] = Bu[(kb + gt + 4) * BS_STRIDE + c];
            }
            #pragma unroll
            for (int mi = 0; mi < 4; mi++)
                #pragma unroll
                for (int ni = 0; ni < 4; ni++)
                    mma_tf32(acc[mi][ni],
                             af[mi][0], af[mi][1], af[mi][2], af[mi][3],
                             bf[ni][0], bf[ni][1]);
        }
    }

    #pragma unroll
    for (int mi = 0; mi < 4; mi++) {
        int r = row0 + wm * 64 + mi * 16 + gq;
        #pragma unroll
        for (int ni = 0; ni < 4; ni++) {
            int c = col0 + wn * 32 + ni * 8 + gt * 2;
            float v0 = acc[mi][ni][0], v1 = acc[mi][ni][1];
            float v2 = acc[mi][ni][2], v3 = acc[mi][ni][3];
            if (EPI >= 1) {
                float b0 = bias[c], b1 = bias[c + 1];
                v0 += b0; v1 += b1; v2 += b0; v3 += b1;
            }
            if (EPI == 1) {
                const float2 r01 = *(const float2*)&res[(size_t) r      * N + c];
                const float2 r23 = *(const float2*)&res[(size_t)(r + 8) * N + c];
                v0 += r01.x; v1 += r01.y; v2 += r23.x; v3 += r23.y;
            }
            if (EPI == 2) {
                v0 = round_tf32(0.5f * v0 * (1.0f + erff(v0 * 0.70710678118f)));
                v1 = round_tf32(0.5f * v1 * (1.0f + erff(v1 * 0.70710678118f)));
                v2 = round_tf32(0.5f * v2 * (1.0f + erff(v2 * 0.70710678118f)));
                v3 = round_tf32(0.5f * v3 * (1.0f + erff(v3 * 0.70710678118f)));
            }
            *(float2*)&C[(size_t) r      * N + c] = make_float2(v0, v1);
            *(float2*)&C[(size_t)(r + 8) * N + c] = make_float2(v2, v3);
        }
    }
}

// ---------------------------------------------------------------------------
// Tensor-core flash attention (tf32 mma, online softmax in fragments).
// Grid: (32 q-tiles, 12 heads, 2 batch). 128 threads = 4 warps.
// Output tf32-rounded (feeds proj GEMM).
// ---------------------------------------------------------------------------
#define KST 68
#define VST 72
#define SM_QP 0
#define SM_K  (64 * KST)
#define SM_V  (SM_K + 2 * 64 * KST)
#define ATTN_SMEM_FLOATS (SM_V + 2 * 64 * VST)

__global__ __launch_bounds__(128) void attn_tc(
    const float* __restrict__ qkv, float* __restrict__ o)
{
    extern __shared__ float sm[];
    float* QP = sm + SM_QP;
    float* Ks = sm + SM_K;
    float* Vs = sm + SM_V;

    int tid  = threadIdx.x;
    int lane = tid & 31;
    int warp = tid >> 5;
    int gq   = lane >> 2;   // 0..7
    int gt   = lane & 3;    // 0..3
    int wr   = warp * 16;

    int qt = blockIdx.x, h = blockIdx.y, b = blockIdx.z;
    int q_tok0 = b * NSEQ + qt * 64;
    int qcol = h * HD;
    int kcol = DIM + h * HD;
    int vcol = 2 * DIM + h * HD;
    const float scale = 0.125f;

    auto load_kv = [&](int kt, int buf) {
        int k_tok0 = b * NSEQ + kt * 64;
        #pragma unroll
        for (int i = 0; i < 8; i++) {
            int e = tid + i * 128;
            int r = e >> 4, c4 = e & 15;
            const float* gk = qkv + (size_t)(k_tok0 + r) * H3 + kcol + c4 * 4;
            const float* gv = qkv + (size_t)(k_tok0 + r) * H3 + vcol + c4 * 4;
            cp_async16((uint32_t)__cvta_generic_to_shared(
                &Ks[buf * 64 * KST + r * KST + c4 * 4]), gk);
            cp_async16((uint32_t)__cvta_generic_to_shared(
                &Vs[buf * 64 * VST + r * VST + c4 * 4]), gv);
        }
        cp_commit();
    };

    load_kv(0, 0);

    #pragma unroll
    for (int i = 0; i < 8; i++) {
        int e = tid + i * 128;
        int r = e >> 4, c4 = e & 15;
        float4 v = *(const float4*)(qkv + (size_t)(q_tok0 + r) * H3 + qcol + c4 * 4);
        v.x *= scale; v.y *= scale; v.z *= scale; v.w *= scale;
        *(float4*)&QP[r * KST + c4 * 4] = v;
    }
    __syncthreads();

    uint32_t qf[8][4];
    #pragma unroll
    for (int ks = 0; ks < 8; ks++) {
        int kb = ks * 8;
        qf[ks][0] = f2tf32(QP[(wr + gq    ) * KST + kb + gt    ]);
        qf[ks][1] = f2tf32(QP[(wr + gq + 8) * KST + kb + gt    ]);
        qf[ks][2] = f2tf32(QP[(wr + gq    ) * KST + kb + gt + 4]);
        qf[ks][3] = f2tf32(QP[(wr + gq + 8) * KST + kb + gt + 4]);
    }
    __syncthreads();

    float* Ps = QP + warp * 16 * KST;

    float m0 = -1e30f, m1 = -1e30f, l0 = 0.f, l1 = 0.f;
    float oacc[8][4];
    #pragma unroll
    for (int nf = 0; nf < 8; nf++)
        #pragma unroll
        for (int j = 0; j < 4; j++) oacc[nf][j] = 0.f;

    for (int kt = 0; kt < NSEQ / 64; kt++) {
        cp_wait<0>();
        __syncthreads();
        if (kt + 1 < NSEQ / 64) load_kv(kt + 1, (kt + 1) & 1);
        const float* Kb = Ks + (kt & 1) * 64 * KST;
        const float* Vb = Vs + (kt & 1) * 64 * VST;

        float sacc[8][4];
        #pragma unroll
        for (int nf = 0; nf < 8; nf++)
            #pragma unroll
            for (int j = 0; j < 4; j++) sacc[nf][j] = 0.f;

        #pragma unroll
        for (int ks = 0; ks < 8; ks++) {
            int kb = ks * 8;
            #pragma unroll
            for (int nf = 0; nf < 8; nf++) {
                uint32_t b0 = f2tf32(Kb[(nf * 8 + gq) * KST + kb + gt    ]);
                uint32_t b1 = f2tf32(Kb[(nf * 8 + gq) * KST + kb + gt + 4]);
                mma_tf32(sacc[nf], qf[ks][0], qf[ks][1], qf[ks][2], qf[ks][3], b0, b1);
            }
        }

        float mx0 = -1e30f, mx1 = -1e30f;
        #pragma unroll
        for (int nf = 0; nf < 8; nf++) {
            mx0 = fmaxf(mx0, fmaxf(sacc[nf][0], sacc[nf][1]));
            mx1 = fmaxf(mx1, fmaxf(sacc[nf][2], sacc[nf][3]));
        }
        mx0 = fmaxf(mx0, __shfl_xor_sync(0xffffffffu, mx0, 1));
        mx0 = fmaxf(mx0, __shfl_xor_sync(0xffffffffu, mx0, 2));
        mx1 = fmaxf(mx1, __shfl_xor_sync(0xffffffffu, mx1, 1));
        mx1 = fmaxf(mx1, __shfl_xor_sync(0xffffffffu, mx1, 2));

        float mn0 = fmaxf(m0, mx0), mn1 = fmaxf(m1, mx1);
        float alpha0 = __expf(m0 - mn0), alpha1 = __expf(m1 - mn1);
        m0 = mn0; m1 = mn1;

        float sum0 = 0.f, sum1 = 0.f;
        #pragma unroll
        for (int nf = 0; nf < 8; nf++) {
            float p0 = __expf(sacc[nf][0] - mn0);
            float p1 = __expf(sacc[nf][1] - mn0);
            float p2 = __expf(sacc[nf][2] - mn1);
            float p3 = __expf(sacc[nf][3] - mn1);
            sum0 += p0 + p1; sum1 += p2 + p3;
            *(float2*)&Ps[ gq      * KST + nf * 8 + gt * 2] = make_float2(p0, p1);
            *(float2*)&Ps[(gq + 8) * KST + nf * 8 + gt * 2] = make_float2(p2, p3);
        }
        sum0 += __shfl_xor_sync(0xffffffffu, sum0, 1);
        sum0 += __shfl_xor_sync(0xffffffffu, sum0, 2);
        sum1 += __shfl_xor_sync(0xffffffffu, sum1, 1);
        sum1 += __shfl_xor_sync(0xffffffffu, sum1, 2);
        l0 = l0 * alpha0 + sum0;
        l1 = l1 * alpha1 + sum1;

        #pragma unroll
        for (int nf = 0; nf < 8; nf++) {
            oacc[nf][0] *= alpha0; oacc[nf][1] *= alpha0;
            oacc[nf][2] *= alpha1; oacc[nf][3] *= alpha1;
        }
        __syncwarp();

        #pragma unroll
        for (int ks = 0; ks < 8; ks++) {
            int kb = ks * 8;
            uint32_t a0 = f2tf32(Ps[ gq      * KST + kb + gt    ]);
            uint32_t a1 = f2tf32(Ps[(gq + 8) * KST + kb + gt    ]);
            uint32_t a2 = f2tf32(Ps[ gq      * KST + kb + gt + 4]);
            uint32_t a3 = f2tf32(Ps[(gq + 8) * KST + kb + gt + 4]);
            #pragma unroll
            for (int nf = 0; nf < 8; nf++) {
                uint32_t b0 = f2tf32(Vb[(kb + gt    ) * VST + nf * 8 + gq]);
                uint32_t b1 = f2tf32(Vb[(kb + gt + 4) * VST + nf * 8 + gq]);
                mma_tf32(oacc[nf], a0, a1, a2, a3, b0, b1);
            }
        }
        __syncwarp();
    }

    float invl0 = 1.0f / l0, invl1 = 1.0f / l1;
    int r0 = q_tok0 + wr + gq;
    #pragma unroll
    for (int nf = 0; nf < 8; nf++) {
        int c = h * HD + nf * 8 + gt * 2;
        *(float2*)&o[(size_t) r0      * DIM + c] = make_float2(
            round_tf32(oacc[nf][0] * invl0), round_tf32(oacc[nf][1] * invl0));
        *(float2*)&o[(size_t)(r0 + 8) * DIM + c] = make_float2(
            round_tf32(oacc[nf][2] * invl1), round_tf32(oacc[nf][3] * invl1));
    }
}

// ---------------------------------------------------------------------------
// Launch
// ---------------------------------------------------------------------------
extern "C" void kernel_launch(void* const* d_in, const int* in_sizes, int n_in,
                              void* d_out, int out_size)
{
    const float* x      = (const float*)d_in[0];
    const float* ln1_g  = (const float*)d_in[1];
    const float* ln1_b  = (const float*)d_in[2];
    const float* w_qkv  = (const float*)d_in[3];
    const float* w_proj = (const float*)d_in[4];
    const float* b_proj = (const float*)d_in[5];
    const float* ln2_g  = (const float*)d_in[6];
    const float* ln2_b  = (const float*)d_in[7];
    const float* w_fc1  = (const float*)d_in[8];
    const float* b_fc1  = (const float*)d_in[9];
    const float* w_fc2  = (const float*)d_in[10];
    const float* b_fc2  = (const float*)d_in[11];
    float* out = (float*)d_out;

    float *p_h, *p_qkv, *p_o, *p_x1, *p_h2, *p_m;
    float *p_wq, *p_wp, *p_w1, *p_w2;
    cudaGetSymbolAddress((void**)&p_h,   g_h);
    cudaGetSymbolAddress((void**)&p_qkv, g_qkv);
    cudaGetSymbolAddress((void**)&p_o,   g_o);
    cudaGetSymbolAddress((void**)&p_x1,  g_x1);
    cudaGetSymbolAddress((void**)&p_h2,  g_h2);
    cudaGetSymbolAddress((void**)&p_m,   g_m);
    cudaGetSymbolAddress((void**)&p_wq,  g_wq);
    cudaGetSymbolAddress((void**)&p_wp,  g_wp);
    cudaGetSymbolAddress((void**)&p_w1,  g_w1);
    cudaGetSymbolAddress((void**)&p_w2,  g_w2);

    const int attn_smem = ATTN_SMEM_FLOATS * (int)sizeof(float); // ~87 KB
    cudaFuncSetAttribute(attn_tc,
                         cudaFuncAttributeMaxDynamicSharedMemorySize, attn_smem);

    // 0. Pre-round weights to tf32 (once per launch)
    {
        int n;
        n = DIM * H3  / 4; round_w_kernel<<<(n + 255) / 256, 256>>>((const float4*)w_qkv,  (float4*)p_wq, n);
        n = DIM * DIM / 4; round_w_kernel<<<(n + 255) / 256, 256>>>((const float4*)w_proj, (float4*)p_wp, n);
        n = DIM * HID / 4; round_w_kernel<<<(n + 255) / 256, 256>>>((const float4*)w_fc1,  (float4*)p_w1, n);
        n = HID * DIM / 4; round_w_kernel<<<(n + 255) / 256, 256>>>((const float4*)w_fc2,  (float4*)p_w2, n);
    }

    // 1. LN1 (tf32-rounded out)
    ln_kernel<<<TOK, 256>>>(x, ln1_g, ln1_b, p_h);
    // 2. QKV GEMM: [4096,768] @ [768,2304]
    gemm_tc<0><<<dim3(H3 / 128, TOK / 128), 256>>>(
        p_h, p_wq, nullptr, nullptr, p_qkv, TOK, H3, DIM);
    // 3. Attention (tensor cores, tf32-rounded out)
    attn_tc<<<dim3(NSEQ / 64, NHEAD, 2), 128, attn_smem>>>(p_qkv, p_o);
    // 4. Proj GEMM + bias + residual(x) -> full fp32
    gemm_tc<1><<<dim3(DIM / 128, TOK / 128), 256>>>(
        p_o, p_wp, b_proj, x, p_x1, TOK, DIM, DIM);
    // 5. LN2 (tf32-rounded out)
    ln_kernel<<<TOK, 256>>>(p_x1, ln2_g, ln2_b, p_h2);
    // 6. FC1 GEMM + bias + GELU (tf32-rounded out)
    gemm_tc<2><<<dim3(HID / 128, TOK / 128), 256>>>(
        p_h2, p_w1, b_fc1, nullptr, p_m, TOK, HID, DIM);
    // 7. FC2 GEMM + bias + residual(x1) -> d_out (full fp32)
    gemm_tc<1><<<dim3(DIM / 128, TOK / 128), 256>>>(
        p_m, p_w2, b_fc2, p_x1, out, TOK, DIM, HID);
}

// round 5
// speedup vs baseline: 3.2820x; 1.0570x over previous
#include <cuda_runtime.h>
#include <math.h>
#include <stdint.h>

// Problem constants
#define TOK   4096      // 2 * 2048 tokens
#define NSEQ  2048
#define DIM   768
#define H3    2304      // 3*DIM
#define HID   3072
#define NHEAD 12
#define HD    64

// Scratch (no allocations allowed -> __device__ globals). 16B+ aligned for cp.async.
__device__ __align__(128) float g_h  [TOK * DIM];   // LN1 out (tf32-rounded)
__device__ __align__(128) float g_qkv[TOK * H3];    // qkv
__device__ __align__(128) float g_o  [TOK * DIM];   // attention out (tf32-rounded)
__device__ __align__(128) float g_x1 [TOK * DIM];   // x + proj (full fp32)
__device__ __align__(128) float g_h2 [TOK * DIM];   // LN2 out (tf32-rounded)
__device__ __align__(128) float g_m  [TOK * HID];   // gelu(fc1) (tf32-rounded)
// tf32-rounded weight copies
__device__ __align__(128) float g_wq [DIM * H3];
__device__ __align__(128) float g_wp [DIM * DIM];
__device__ __align__(128) float g_w1 [DIM * HID];
__device__ __align__(128) float g_w2 [HID * DIM];

// ---------------------------------------------------------------------------
// PTX helpers
// ---------------------------------------------------------------------------
__device__ __forceinline__ uint32_t f2tf32(float f) {
    uint32_t u;
    asm("cvt.rna.tf32.f32 %0, %1;" : "=r"(u) : "f"(f));
    return u;
}
__device__ __forceinline__ float round_tf32(float f) {
    return __uint_as_float(f2tf32(f));
}

__device__ __forceinline__ void mma_tf32(float* d,
    uint32_t a0, uint32_t a1, uint32_t a2, uint32_t a3,
    uint32_t b0, uint32_t b1)
{
    asm volatile(
        "mma.sync.aligned.m16n8k8.row.col.f32.tf32.tf32.f32 "
        "{%0,%1,%2,%3}, {%4,%5,%6,%7}, {%8,%9}, {%0,%1,%2,%3};"
        : "+f"(d[0]), "+f"(d[1]), "+f"(d[2]), "+f"(d[3])
        : "r"(a0), "r"(a1), "r"(a2), "r"(a3), "r"(b0), "r"(b1));
}

__device__ __forceinline__ void cp_async16(uint32_t s, const void* g) {
    asm volatile("cp.async.cg.shared.global [%0], [%1], 16;" :: "r"(s), "l"(g));
}
__device__ __forceinline__ void cp_commit() {
    asm volatile("cp.async.commit_group;" ::);
}
template<int N>
__device__ __forceinline__ void cp_wait() {
    asm volatile("cp.async.wait_group %0;" :: "n"(N));
}

// ---------------------------------------------------------------------------
// Weight pre-rounding to tf32 (once per launch)
// ---------------------------------------------------------------------------
__global__ __launch_bounds__(256) void round_w_kernel(
    const float4* __restrict__ src, float4* __restrict__ dst, int n4)
{
    int i = blockIdx.x * 256 + threadIdx.x;
    if (i < n4) {
        float4 v = src[i];
        v.x = round_tf32(v.x); v.y = round_tf32(v.y);
        v.z = round_tf32(v.z); v.w = round_tf32(v.w);
        dst[i] = v;
    }
}

// ---------------------------------------------------------------------------
// LayerNorm: one block per row of 768, 256 threads. Output tf32-rounded.
// ---------------------------------------------------------------------------
__global__ __launch_bounds__(256) void ln_kernel(
    const float* __restrict__ x, const float* __restrict__ g,
    const float* __restrict__ b, float* __restrict__ out)
{
    int row = blockIdx.x;
    int t   = threadIdx.x;
    const float* xr = x + row * DIM;

    float v0 = xr[t], v1 = xr[t + 256], v2 = xr[t + 512];
    float s = v0 + v1 + v2;
    float q = v0 * v0 + v1 * v1 + v2 * v2;

    __shared__ float rs[8], rq[8];
    #pragma unroll
    for (int o = 16; o; o >>= 1) {
        s += __shfl_xor_sync(0xffffffffu, s, o);
        q += __shfl_xor_sync(0xffffffffu, q, o);
    }
    if ((t & 31) == 0) { rs[t >> 5] = s; rq[t >> 5] = q; }
    __syncthreads();

    __shared__ float smu, srstd;
    if (t == 0) {
        float S = 0.f, Q = 0.f;
        #pragma unroll
        for (int i = 0; i < 8; i++) { S += rs[i]; Q += rq[i]; }
        float mu  = S * (1.0f / DIM);
        float var = Q * (1.0f / DIM) - mu * mu;
        smu = mu;
        srstd = rsqrtf(var + 1e-5f);
    }
    __syncthreads();
    float mu = smu, r = srstd;
    float* orow = out + row * DIM;
    orow[t]       = round_tf32((v0 - mu) * r * g[t]       + b[t]);
    orow[t + 256] = round_tf32((v1 - mu) * r * g[t + 256] + b[t + 256]);
    orow[t + 512] = round_tf32((v2 - mu) * r * g[t + 512] + b[t + 512]);
}

// ---------------------------------------------------------------------------
// TF32 tensor-core GEMM, inputs PRE-ROUNDED to tf32.
// CTA tile 128x128, BK=16, 128 threads = 4 warps in 2x2, warp tile 64x64.
// 3-stage cp.async pipeline, dynamic smem (2 CTAs/SM).
// EPI: 0 = none, 1 = bias + residual, 2 = bias + exact GELU (tf32-rounded out)
// ---------------------------------------------------------------------------
#define AS_STRIDE 20    // 16 + 4 pad (bank set conflict-free for A frags)
#define BS_STRIDE 136   // 128 + 8 pad: ≡8 mod 32 -> conflict-free B frags
#define STAGES 3
#define GEMM_STAGE_FLOATS (128 * AS_STRIDE + 16 * BS_STRIDE)   // 2560+2176=4736
#define GEMM_SMEM_BYTES (STAGES * GEMM_STAGE_FLOATS * 4)       // 56832

template<int EPI>
__global__ __launch_bounds__(128) void gemm_tc(
    const float* __restrict__ A, const float* __restrict__ B,
    const float* __restrict__ bias, const float* __restrict__ res,
    float* __restrict__ C, int M, int N, int K)
{
    extern __shared__ float gsm[];

    int tid  = threadIdx.x;
    int lane = tid & 31;
    int warp = tid >> 5;
    int wm = warp >> 1;       // 0..1
    int wn = warp & 1;        // 0..1
    int row0 = blockIdx.y * 128;
    int col0 = blockIdx.x * 128;

    float acc[4][8][4];
    #pragma unroll
    for (int mi = 0; mi < 4; mi++)
        #pragma unroll
        for (int nf = 0; nf < 8; nf++)
            #pragma unroll
            for (int j = 0; j < 4; j++) acc[mi][nf][j] = 0.f;

    int gq = lane >> 2;
    int gt = lane & 3;

    auto load_tile = [&](int k0, int buf) {
        float* As = gsm + buf * GEMM_STAGE_FLOATS;
        float* Bs = As + 128 * AS_STRIDE;
        #pragma unroll
        for (int i = 0; i < 4; i++) {
            int e = tid + i * 128;          // 0..511
            int r = e >> 2, c4 = e & 3;
            cp_async16((uint32_t)__cvta_generic_to_shared(
                &As[r * AS_STRIDE + c4 * 4]),
                A + (size_t)(row0 + r) * K + k0 + c4 * 4);
        }
        #pragma unroll
        for (int i = 0; i < 4; i++) {
            int e = tid + i * 128;
            int r = e >> 5, c4 = e & 31;
            cp_async16((uint32_t)__cvta_generic_to_shared(
                &Bs[r * BS_STRIDE + c4 * 4]),
                B + (size_t)(k0 + r) * N + col0 + c4 * 4);
        }
        cp_commit();
    };

    int ntiles = K / 16;
    load_tile(0, 0);
    load_tile(16, 1);

    for (int t = 0; t < ntiles; t++) {
        cp_wait<STAGES - 2>();
        __syncthreads();
        if (t + 2 < ntiles) load_tile((t + 2) * 16, (t + 2) % STAGES);
        int buf = t % STAGES;

        const uint32_t* Au = (const uint32_t*)(gsm + buf * GEMM_STAGE_FLOATS);
        const uint32_t* Bu = Au + 128 * AS_STRIDE;

        #pragma unroll
        for (int ks = 0; ks < 2; ks++) {
            int kb = ks * 8;
            uint32_t af[4][4];
            #pragma unroll
            for (int mi = 0; mi < 4; mi++) {
                int r = wm * 64 + mi * 16 + gq;
                af[mi][0] = Au[ r      * AS_STRIDE + kb + gt    ];
                af[mi][1] = Au[(r + 8) * AS_STRIDE + kb + gt    ];
                af[mi][2] = Au[ r      * AS_STRIDE + kb + gt + 4];
                af[mi][3] = Au[(r + 8) * AS_STRIDE + kb + gt + 4];
            }
            uint32_t bf[8][2];
            #pragma unroll
            for (int nf = 0; nf < 8; nf++) {
                int c = wn * 64 + nf * 8 + gq;
                bf[nf][0] = Bu[(kb + gt    ) * BS_STRIDE + c];
                bf[nf][1] = Bu[(kb + gt + 4) * BS_STRIDE + c];
            }
            #pragma unroll
            for (int mi = 0; mi < 4; mi++)
                #pragma unroll
                for (int nf = 0; nf < 8; nf++)
                    mma_tf32(acc[mi][nf],
                             af[mi][0], af[mi][1], af[mi][2], af[mi][3],
                             bf[nf][0], bf[nf][1]);
        }
    }

    #pragma unroll
    for (int mi = 0; mi < 4; mi++) {
        int r = row0 + wm * 64 + mi * 16 + gq;
        #pragma unroll
        for (int nf = 0; nf < 8; nf++) {
            int c = col0 + wn * 64 + nf * 8 + gt * 2;
            float v0 = acc[mi][nf][0], v1 = acc[mi][nf][1];
            float v2 = acc[mi][nf][2], v3 = acc[mi][nf][3];
            if (EPI >= 1) {
                float b0 = bias[c], b1 = bias[c + 1];
                v0 += b0; v1 += b1; v2 += b0; v3 += b1;
            }
            if (EPI == 1) {
                const float2 r01 = *(const float2*)&res[(size_t) r      * N + c];
                const float2 r23 = *(const float2*)&res[(size_t)(r + 8) * N + c];
                v0 += r01.x; v1 += r01.y; v2 += r23.x; v3 += r23.y;
            }
            if (EPI == 2) {
                v0 = round_tf32(0.5f * v0 * (1.0f + erff(v0 * 0.70710678118f)));
                v1 = round_tf32(0.5f * v1 * (1.0f + erff(v1 * 0.70710678118f)));
                v2 = round_tf32(0.5f * v2 * (1.0f + erff(v2 * 0.70710678118f)));
                v3 = round_tf32(0.5f * v3 * (1.0f + erff(v3 * 0.70710678118f)));
            }
            *(float2*)&C[(size_t) r      * N + c] = make_float2(v0, v1);
            *(float2*)&C[(size_t)(r + 8) * N + c] = make_float2(v2, v3);
        }
    }
}

// ---------------------------------------------------------------------------
// Tensor-core flash attention (tf32 mma, online softmax in fragments).
// Grid: (32 q-tiles, 12 heads, 2 batch). 128 threads = 4 warps.
// ---------------------------------------------------------------------------
#define KST 68
#define VST 72
#define SM_QP 0
#define SM_K  (64 * KST)
#define SM_V  (SM_K + 2 * 64 * KST)
#define ATTN_SMEM_FLOATS (SM_V + 2 * 64 * VST)

__global__ __launch_bounds__(128) void attn_tc(
    const float* __restrict__ qkv, float* __restrict__ o)
{
    extern __shared__ float sm[];
    float* QP = sm + SM_QP;
    float* Ks = sm + SM_K;
    float* Vs = sm + SM_V;

    int tid  = threadIdx.x;
    int lane = tid & 31;
    int warp = tid >> 5;
    int gq   = lane >> 2;
    int gt   = lane & 3;
    int wr   = warp * 16;

    int qt = blockIdx.x, h = blockIdx.y, b = blockIdx.z;
    int q_tok0 = b * NSEQ + qt * 64;
    int qcol = h * HD;
    int kcol = DIM + h * HD;
    int vcol = 2 * DIM + h * HD;
    const float scale = 0.125f;

    auto load_kv = [&](int kt, int buf) {
        int k_tok0 = b * NSEQ + kt * 64;
        #pragma unroll
        for (int i = 0; i < 8; i++) {
            int e = tid + i * 128;
            int r = e >> 4, c4 = e & 15;
            const float* gk = qkv + (size_t)(k_tok0 + r) * H3 + kcol + c4 * 4;
            const float* gv = qkv + (size_t)(k_tok0 + r) * H3 + vcol + c4 * 4;
            cp_async16((uint32_t)__cvta_generic_to_shared(
                &Ks[buf * 64 * KST + r * KST + c4 * 4]), gk);
            cp_async16((uint32_t)__cvta_generic_to_shared(
                &Vs[buf * 64 * VST + r * VST + c4 * 4]), gv);
        }
        cp_commit();
    };

    load_kv(0, 0);

    #pragma unroll
    for (int i = 0; i < 8; i++) {
        int e = tid + i * 128;
        int r = e >> 4, c4 = e & 15;
        float4 v = *(const float4*)(qkv + (size_t)(q_tok0 + r) * H3 + qcol + c4 * 4);
        v.x *= scale; v.y *= scale; v.z *= scale; v.w *= scale;
        *(float4*)&QP[r * KST + c4 * 4] = v;
    }
    __syncthreads();

    uint32_t qf[8][4];
    #pragma unroll
    for (int ks = 0; ks < 8; ks++) {
        int kb = ks * 8;
        qf[ks][0] = f2tf32(QP[(wr + gq    ) * KST + kb + gt    ]);
        qf[ks][1] = f2tf32(QP[(wr + gq + 8) * KST + kb + gt    ]);
        qf[ks][2] = f2tf32(QP[(wr + gq    ) * KST + kb + gt + 4]);
        qf[ks][3] = f2tf32(QP[(wr + gq + 8) * KST + kb + gt + 4]);
    }
    __syncthreads();

    float* Ps = QP + warp * 16 * KST;

    float m0 = -1e30f, m1 = -1e30f, l0 = 0.f, l1 = 0.f;
    float oacc[8][4];
    #pragma unroll
    for (int nf = 0; nf < 8; nf++)
        #pragma unroll
        for (int j = 0; j < 4; j++) oacc[nf][j] = 0.f;

    for (int kt = 0; kt < NSEQ / 64; kt++) {
        cp_wait<0>();
        __syncthreads();
        if (kt + 1 < NSEQ / 64) load_kv(kt + 1, (kt + 1) & 1);
        const float* Kb = Ks + (kt & 1) * 64 * KST;
        const float* Vb = Vs + (kt & 1) * 64 * VST;

        float sacc[8][4];
        #pragma unroll
        for (int nf = 0; nf < 8; nf++)
            #pragma unroll
            for (int j = 0; j < 4; j++) sacc[nf][j] = 0.f;

        #pragma unroll
        for (int ks = 0; ks < 8; ks++) {
            int kb = ks * 8;
            #pragma unroll
            for (int nf = 0; nf < 8; nf++) {
                uint32_t b0 = f2tf32(Kb[(nf * 8 + gq) * KST + kb + gt    ]);
                uint32_t b1 = f2tf32(Kb[(nf * 8 + gq) * KST + kb + gt + 4]);
                mma_tf32(sacc[nf], qf[ks][0], qf[ks][1], qf[ks][2], qf[ks][3], b0, b1);
            }
        }

        float mx0 = -1e30f, mx1 = -1e30f;
        #pragma unroll
        for (int nf = 0; nf < 8; nf++) {
            mx0 = fmaxf(mx0, fmaxf(sacc[nf][0], sacc[nf][1]));
            mx1 = fmaxf(mx1, fmaxf(sacc[nf][2], sacc[nf][3]));
        }
        mx0 = fmaxf(mx0, __shfl_xor_sync(0xffffffffu, mx0, 1));
        mx0 = fmaxf(mx0, __shfl_xor_sync(0xffffffffu, mx0, 2));
        mx1 = fmaxf(mx1, __shfl_xor_sync(0xffffffffu, mx1, 1));
        mx1 = fmaxf(mx1, __shfl_xor_sync(0xffffffffu, mx1, 2));

        float mn0 = fmaxf(m0, mx0), mn1 = fmaxf(m1, mx1);
        float alpha0 = __expf(m0 - mn0), alpha1 = __expf(m1 - mn1);
        m0 = mn0; m1 = mn1;

        float sum0 = 0.f, sum1 = 0.f;
        #pragma unroll
        for (int nf = 0; nf < 8; nf++) {
            float p0 = __expf(sacc[nf][0] - mn0);
            float p1 = __expf(sacc[nf][1] - mn0);
            float p2 = __expf(sacc[nf][2] - mn1);
            float p3 = __expf(sacc[nf][3] - mn1);
            sum0 += p0 + p1; sum1 += p2 + p3;
            *(float2*)&Ps[ gq      * KST + nf * 8 + gt * 2] = make_float2(p0, p1);
            *(float2*)&Ps[(gq + 8) * KST + nf * 8 + gt * 2] = make_float2(p2, p3);
        }
        sum0 += __shfl_xor_sync(0xffffffffu, sum0, 1);
        sum0 += __shfl_xor_sync(0xffffffffu, sum0, 2);
        sum1 += __shfl_xor_sync(0xffffffffu, sum1, 1);
        sum1 += __shfl_xor_sync(0xffffffffu, sum1, 2);
        l0 = l0 * alpha0 + sum0;
        l1 = l1 * alpha1 + sum1;

        #pragma unroll
        for (int nf = 0; nf < 8; nf++) {
            oacc[nf][0] *= alpha0; oacc[nf][1] *= alpha0;
            oacc[nf][2] *= alpha1; oacc[nf][3] *= alpha1;
        }
        __syncwarp();

        #pragma unroll
        for (int ks = 0; ks < 8; ks++) {
            int kb = ks * 8;
            uint32_t a0 = f2tf32(Ps[ gq      * KST + kb + gt    ]);
            uint32_t a1 = f2tf32(Ps[(gq + 8) * KST + kb + gt    ]);
            uint32_t a2 = f2tf32(Ps[ gq      * KST + kb + gt + 4]);
            uint32_t a3 = f2tf32(Ps[(gq + 8) * KST + kb + gt + 4]);
            #pragma unroll
            for (int nf = 0; nf < 8; nf++) {
                uint32_t b0 = f2tf32(Vb[(kb + gt    ) * VST + nf * 8 + gq]);
                uint32_t b1 = f2tf32(Vb[(kb + gt + 4) * VST + nf * 8 + gq]);
                mma_tf32(oacc[nf], a0, a1, a2, a3, b0, b1);
            }
        }
        __syncwarp();
    }

    float invl0 = 1.0f / l0, invl1 = 1.0f / l1;
    int r0 = q_tok0 + wr + gq;
    #pragma unroll
    for (int nf = 0; nf < 8; nf++) {
        int c = h * HD + nf * 8 + gt * 2;
        *(float2*)&o[(size_t) r0      * DIM + c] = make_float2(
            round_tf32(oacc[nf][0] * invl0), round_tf32(oacc[nf][1] * invl0));
        *(float2*)&o[(size_t)(r0 + 8) * DIM + c] = make_float2(
            round_tf32(oacc[nf][2] * invl1), round_tf32(oacc[nf][3] * invl1));
    }
}

// ---------------------------------------------------------------------------
// Launch
// ---------------------------------------------------------------------------
extern "C" void kernel_launch(void* const* d_in, const int* in_sizes, int n_in,
                              void* d_out, int out_size)
{
    const float* x      = (const float*)d_in[0];
    const float* ln1_g  = (const float*)d_in[1];
    const float* ln1_b  = (const float*)d_in[2];
    const float* w_qkv  = (const float*)d_in[3];
    const float* w_proj = (const float*)d_in[4];
    const float* b_proj = (const float*)d_in[5];
    const float* ln2_g  = (const float*)d_in[6];
    const float* ln2_b  = (const float*)d_in[7];
    const float* w_fc1  = (const float*)d_in[8];
    const float* b_fc1  = (const float*)d_in[9];
    const float* w_fc2  = (const float*)d_in[10];
    const float* b_fc2  = (const float*)d_in[11];
    float* out = (float*)d_out;

    float *p_h, *p_qkv, *p_o, *p_x1, *p_h2, *p_m;
    float *p_wq, *p_wp, *p_w1, *p_w2;
    cudaGetSymbolAddress((void**)&p_h,   g_h);
    cudaGetSymbolAddress((void**)&p_qkv, g_qkv);
    cudaGetSymbolAddress((void**)&p_o,   g_o);
    cudaGetSymbolAddress((void**)&p_x1,  g_x1);
    cudaGetSymbolAddress((void**)&p_h2,  g_h2);
    cudaGetSymbolAddress((void**)&p_m,   g_m);
    cudaGetSymbolAddress((void**)&p_wq,  g_wq);
    cudaGetSymbolAddress((void**)&p_wp,  g_wp);
    cudaGetSymbolAddress((void**)&p_w1,  g_w1);
    cudaGetSymbolAddress((void**)&p_w2,  g_w2);

    const int attn_smem = ATTN_SMEM_FLOATS * (int)sizeof(float); // ~87 KB
    cudaFuncSetAttribute(attn_tc,
                         cudaFuncAttributeMaxDynamicSharedMemorySize, attn_smem);
    cudaFuncSetAttribute(gemm_tc<0>,
                         cudaFuncAttributeMaxDynamicSharedMemorySize, GEMM_SMEM_BYTES);
    cudaFuncSetAttribute(gemm_tc<1>,
                         cudaFuncAttributeMaxDynamicSharedMemorySize, GEMM_SMEM_BYTES);
    cudaFuncSetAttribute(gemm_tc<2>,
                         cudaFuncAttributeMaxDynamicSharedMemorySize, GEMM_SMEM_BYTES);

    // 0. Pre-round weights to tf32 (once per launch)
    {
        int n;
        n = DIM * H3  / 4; round_w_kernel<<<(n + 255) / 256, 256>>>((const float4*)w_qkv,  (float4*)p_wq, n);
        n = DIM * DIM / 4; round_w_kernel<<<(n + 255) / 256, 256>>>((const float4*)w_proj, (float4*)p_wp, n);
        n = DIM * HID / 4; round_w_kernel<<<(n + 255) / 256, 256>>>((const float4*)w_fc1,  (float4*)p_w1, n);
        n = HID * DIM / 4; round_w_kernel<<<(n + 255) / 256, 256>>>((const float4*)w_fc2,  (float4*)p_w2, n);
    }

    // 1. LN1 (tf32-rounded out)
    ln_kernel<<<TOK, 256>>>(x, ln1_g, ln1_b, p_h);
    // 2. QKV GEMM: [4096,768] @ [768,2304]
    gemm_tc<0><<<dim3(H3 / 128, TOK / 128), 128, GEMM_SMEM_BYTES>>>(
        p_h, p_wq, nullptr, nullptr, p_qkv, TOK, H3, DIM);
    // 3. Attention (tensor cores, tf32-rounded out)
    attn_tc<<<dim3(NSEQ / 64, NHEAD, 2), 128, attn_smem>>>(p_qkv, p_o);
    // 4. Proj GEMM + bias + residual(x) -> full fp32
    gemm_tc<1><<<dim3(DIM / 128, TOK / 128), 128, GEMM_SMEM_BYTES>>>(
        p_o, p_wp, b_proj, x, p_x1, TOK, DIM, DIM);
    // 5. LN2 (tf32-rounded out)
    ln_kernel<<<TOK, 256>>>(p_x1, ln2_g, ln2_b, p_h2);
    // 6. FC1 GEMM + bias + GELU (tf32-rounded out)
    gemm_tc<2><<<dim3(HID / 128, TOK / 128), 128, GEMM_SMEM_BYTES>>>(
        p_h2, p_w1, b_fc1, nullptr, p_m, TOK, HID, DIM);
    // 7. FC2 GEMM + bias + residual(x1) -> d_out (full fp32)
    gemm_tc<1><<<dim3(DIM / 128, TOK / 128), 128, GEMM_SMEM_BYTES>>>(
        p_m, p_w2, b_fc2, p_x1, out, TOK, DIM, HID);
}

// round 6
// speedup vs baseline: 3.2842x; 1.0007x over previous
#include <cuda_runtime.h>
#include <math.h>
#include <stdint.h>

// Problem constants
#define TOK   4096      // 2 * 2048 tokens
#define NSEQ  2048
#define DIM   768
#define H3    2304      // 3*DIM
#define HID   3072
#define NHEAD 12
#define HD    64

// Scratch (no allocations allowed -> __device__ globals). 16B+ aligned for cp.async.
__device__ __align__(128) float g_h  [TOK * DIM];   // LN1 out (tf32-rounded)
__device__ __align__(128) float g_qkv[TOK * H3];    // qkv
__device__ __align__(128) float g_o  [TOK * DIM];   // attention out (tf32-rounded)
__device__ __align__(128) float g_x1 [TOK * DIM];   // x + proj (full fp32)
__device__ __align__(128) float g_h2 [TOK * DIM];   // LN2 out (tf32-rounded)
__device__ __align__(128) float g_m  [TOK * HID];   // gelu(fc1) (tf32-rounded)
// tf32-rounded weight copies
__device__ __align__(128) float g_wq [DIM * H3];
__device__ __align__(128) float g_wp [DIM * DIM];
__device__ __align__(128) float g_w1 [DIM * HID];
__device__ __align__(128) float g_w2 [HID * DIM];

// ---------------------------------------------------------------------------
// PTX helpers
// ---------------------------------------------------------------------------
__device__ __forceinline__ uint32_t f2tf32(float f) {
    uint32_t u;
    asm("cvt.rna.tf32.f32 %0, %1;" : "=r"(u) : "f"(f));
    return u;
}
__device__ __forceinline__ float round_tf32(float f) {
    return __uint_as_float(f2tf32(f));
}

__device__ __forceinline__ void mma_tf32(float* d,
    uint32_t a0, uint32_t a1, uint32_t a2, uint32_t a3,
    uint32_t b0, uint32_t b1)
{
    asm volatile(
        "mma.sync.aligned.m16n8k8.row.col.f32.tf32.tf32.f32 "
        "{%0,%1,%2,%3}, {%4,%5,%6,%7}, {%8,%9}, {%0,%1,%2,%3};"
        : "+f"(d[0]), "+f"(d[1]), "+f"(d[2]), "+f"(d[3])
        : "r"(a0), "r"(a1), "r"(a2), "r"(a3), "r"(b0), "r"(b1));
}

__device__ __forceinline__ void cp_async16(uint32_t s, const void* g) {
    asm volatile("cp.async.cg.shared.global [%0], [%1], 16;" :: "r"(s), "l"(g));
}
__device__ __forceinline__ void cp_commit() {
    asm volatile("cp.async.commit_group;" ::);
}
template<int N>
__device__ __forceinline__ void cp_wait() {
    asm volatile("cp.async.wait_group %0;" :: "n"(N));
}

// ---------------------------------------------------------------------------
// Weight pre-rounding to tf32 (once per launch)
// ---------------------------------------------------------------------------
__global__ __launch_bounds__(256) void round_w_kernel(
    const float4* __restrict__ src, float4* __restrict__ dst, int n4)
{
    int i = blockIdx.x * 256 + threadIdx.x;
    if (i < n4) {
        float4 v = src[i];
        v.x = round_tf32(v.x); v.y = round_tf32(v.y);
        v.z = round_tf32(v.z); v.w = round_tf32(v.w);
        dst[i] = v;
    }
}

// ---------------------------------------------------------------------------
// LayerNorm: one block per row of 768, 256 threads. Output tf32-rounded.
// ---------------------------------------------------------------------------
__global__ __launch_bounds__(256) void ln_kernel(
    const float* __restrict__ x, const float* __restrict__ g,
    const float* __restrict__ b, float* __restrict__ out)
{
    int row = blockIdx.x;
    int t   = threadIdx.x;
    const float* xr = x + row * DIM;

    float v0 = xr[t], v1 = xr[t + 256], v2 = xr[t + 512];
    float s = v0 + v1 + v2;
    float q = v0 * v0 + v1 * v1 + v2 * v2;

    __shared__ float rs[8], rq[8];
    #pragma unroll
    for (int o = 16; o; o >>= 1) {
        s += __shfl_xor_sync(0xffffffffu, s, o);
        q += __shfl_xor_sync(0xffffffffu, q, o);
    }
    if ((t & 31) == 0) { rs[t >> 5] = s; rq[t >> 5] = q; }
    __syncthreads();

    __shared__ float smu, srstd;
    if (t == 0) {
        float S = 0.f, Q = 0.f;
        #pragma unroll
        for (int i = 0; i < 8; i++) { S += rs[i]; Q += rq[i]; }
        float mu  = S * (1.0f / DIM);
        float var = Q * (1.0f / DIM) - mu * mu;
        smu = mu;
        srstd = rsqrtf(var + 1e-5f);
    }
    __syncthreads();
    float mu = smu, r = srstd;
    float* orow = out + row * DIM;
    orow[t]       = round_tf32((v0 - mu) * r * g[t]       + b[t]);
    orow[t + 256] = round_tf32((v1 - mu) * r * g[t + 256] + b[t + 256]);
    orow[t + 512] = round_tf32((v2 - mu) * r * g[t + 512] + b[t + 512]);
}

// ---------------------------------------------------------------------------
// TF32 tensor-core GEMM, inputs PRE-ROUNDED to tf32.
// CTA tile 128x128, BK=16, 128 threads = 4 warps in 2x2, warp tile 64x64.
// 3-stage cp.async pipeline, dynamic smem (2 CTAs/SM).
// EPI: 0 = none, 1 = bias + residual, 2 = bias + exact GELU (tf32-rounded out)
// ---------------------------------------------------------------------------
#define AS_STRIDE 20    // 16 + 4 pad (bank set conflict-free for A frags)
#define BS_STRIDE 136   // 128 + 8 pad: ≡8 mod 32 -> conflict-free B frags
#define STAGES 3
#define GEMM_STAGE_FLOATS (128 * AS_STRIDE + 16 * BS_STRIDE)   // 2560+2176=4736
#define GEMM_SMEM_BYTES (STAGES * GEMM_STAGE_FLOATS * 4)       // 56832

template<int EPI>
__global__ __launch_bounds__(128) void gemm_tc(
    const float* __restrict__ A, const float* __restrict__ B,
    const float* __restrict__ bias, const float* __restrict__ res,
    float* __restrict__ C, int M, int N, int K)
{
    extern __shared__ float gsm[];

    int tid  = threadIdx.x;
    int lane = tid & 31;
    int warp = tid >> 5;
    int wm = warp >> 1;       // 0..1
    int wn = warp & 1;        // 0..1
    int row0 = blockIdx.y * 128;
    int col0 = blockIdx.x * 128;

    float acc[4][8][4];
    #pragma unroll
    for (int mi = 0; mi < 4; mi++)
        #pragma unroll
        for (int nf = 0; nf < 8; nf++)
            #pragma unroll
            for (int j = 0; j < 4; j++) acc[mi][nf][j] = 0.f;

    int gq = lane >> 2;
    int gt = lane & 3;

    auto load_tile = [&](int k0, int buf) {
        float* As = gsm + buf * GEMM_STAGE_FLOATS;
        float* Bs = As + 128 * AS_STRIDE;
        #pragma unroll
        for (int i = 0; i < 4; i++) {
            int e = tid + i * 128;          // 0..511
            int r = e >> 2, c4 = e & 3;
            cp_async16((uint32_t)__cvta_generic_to_shared(
                &As[r * AS_STRIDE + c4 * 4]),
                A + (size_t)(row0 + r) * K + k0 + c4 * 4);
        }
        #pragma unroll
        for (int i = 0; i < 4; i++) {
            int e = tid + i * 128;
            int r = e >> 5, c4 = e & 31;
            cp_async16((uint32_t)__cvta_generic_to_shared(
                &Bs[r * BS_STRIDE + c4 * 4]),
                B + (size_t)(k0 + r) * N + col0 + c4 * 4);
        }
        cp_commit();
    };

    int ntiles = K / 16;
    load_tile(0, 0);
    load_tile(16, 1);

    for (int t = 0; t < ntiles; t++) {
        cp_wait<STAGES - 2>();
        __syncthreads();
        if (t + 2 < ntiles) load_tile((t + 2) * 16, (t + 2) % STAGES);
        int buf = t % STAGES;

        const uint32_t* Au = (const uint32_t*)(gsm + buf * GEMM_STAGE_FLOATS);
        const uint32_t* Bu = Au + 128 * AS_STRIDE;

        #pragma unroll
        for (int ks = 0; ks < 2; ks++) {
            int kb = ks * 8;
            uint32_t af[4][4];
            #pragma unroll
            for (int mi = 0; mi < 4; mi++) {
                int r = wm * 64 + mi * 16 + gq;
                af[mi][0] = Au[ r      * AS_STRIDE + kb + gt    ];
                af[mi][1] = Au[(r + 8) * AS_STRIDE + kb + gt    ];
                af[mi][2] = Au[ r      * AS_STRIDE + kb + gt + 4];
                af[mi][3] = Au[(r + 8) * AS_STRIDE + kb + gt + 4];
            }
            uint32_t bf[8][2];
            #pragma unroll
            for (int nf = 0; nf < 8; nf++) {
                int c = wn * 64 + nf * 8 + gq;
                bf[nf][0] = Bu[(kb + gt    ) * BS_STRIDE + c];
                bf[nf][1] = Bu[(kb + gt + 4) * BS_STRIDE + c];
            }
            #pragma unroll
            for (int mi = 0; mi < 4; mi++)
                #pragma unroll
                for (int nf = 0; nf < 8; nf++)
                    mma_tf32(acc[mi][nf],
                             af[mi][0], af[mi][1], af[mi][2], af[mi][3],
                             bf[nf][0], bf[nf][1]);
        }
    }

    #pragma unroll
    for (int mi = 0; mi < 4; mi++) {
        int r = row0 + wm * 64 + mi * 16 + gq;
        #pragma unroll
        for (int nf = 0; nf < 8; nf++) {
            int c = col0 + wn * 64 + nf * 8 + gt * 2;
            float v0 = acc[mi][nf][0], v1 = acc[mi][nf][1];
            float v2 = acc[mi][nf][2], v3 = acc[mi][nf][3];
            if (EPI >= 1) {
                float b0 = bias[c], b1 = bias[c + 1];
                v0 += b0; v1 += b1; v2 += b0; v3 += b1;
            }
            if (EPI == 1) {
                const float2 r01 = *(const float2*)&res[(size_t) r      * N + c];
                const float2 r23 = *(const float2*)&res[(size_t)(r + 8) * N + c];
                v0 += r01.x; v1 += r01.y; v2 += r23.x; v3 += r23.y;
            }
            if (EPI == 2) {
                v0 = round_tf32(0.5f * v0 * (1.0f + erff(v0 * 0.70710678118f)));
                v1 = round_tf32(0.5f * v1 * (1.0f + erff(v1 * 0.70710678118f)));
                v2 = round_tf32(0.5f * v2 * (1.0f + erff(v2 * 0.70710678118f)));
                v3 = round_tf32(0.5f * v3 * (1.0f + erff(v3 * 0.70710678118f)));
            }
            *(float2*)&C[(size_t) r      * N + c] = make_float2(v0, v1);
            *(float2*)&C[(size_t)(r + 8) * N + c] = make_float2(v2, v3);
        }
    }
}

// ---------------------------------------------------------------------------
// Tensor-core flash attention (tf32 mma, online softmax in fragments).
// Grid: (32 q-tiles, 12 heads, 2 batch). 128 threads = 4 warps.
// ---------------------------------------------------------------------------
#define KST 68
#define VST 72
#define SM_QP 0
#define SM_K  (64 * KST)
#define SM_V  (SM_K + 2 * 64 * KST)
#define ATTN_SMEM_FLOATS (SM_V + 2 * 64 * VST)

__global__ __launch_bounds__(128) void attn_tc(
    const float* __restrict__ qkv, float* __restrict__ o)
{
    extern __shared__ float sm[];
    float* QP = sm + SM_QP;
    float* Ks = sm + SM_K;
    float* Vs = sm + SM_V;

    int tid  = threadIdx.x;
    int lane = tid & 31;
    int warp = tid >> 5;
    int gq   = lane >> 2;
    int gt   = lane & 3;
    int wr   = warp * 16;

    int qt = blockIdx.x, h = blockIdx.y, b = blockIdx.z;
    int q_tok0 = b * NSEQ + qt * 64;
    int qcol = h * HD;
    int kcol = DIM + h * HD;
    int vcol = 2 * DIM + h * HD;
    const float scale = 0.125f;

    auto load_kv = [&](int kt, int buf) {
        int k_tok0 = b * NSEQ + kt * 64;
        #pragma unroll
        for (int i = 0; i < 8; i++) {
            int e = tid + i * 128;
            int r = e >> 4, c4 = e & 15;
            const float* gk = qkv + (size_t)(k_tok0 + r) * H3 + kcol + c4 * 4;
            const float* gv = qkv + (size_t)(k_tok0 + r) * H3 + vcol + c4 * 4;
            cp_async16((uint32_t)__cvta_generic_to_shared(
                &Ks[buf * 64 * KST + r * KST + c4 * 4]), gk);
            cp_async16((uint32_t)__cvta_generic_to_shared(
                &Vs[buf * 64 * VST + r * VST + c4 * 4]), gv);
        }
        cp_commit();
    };

    load_kv(0, 0);

    #pragma unroll
    for (int i = 0; i < 8; i++) {
        int e = tid + i * 128;
        int r = e >> 4, c4 = e & 15;
        float4 v = *(const float4*)(qkv + (size_t)(q_tok0 + r) * H3 + qcol + c4 * 4);
        v.x *= scale; v.y *= scale; v.z *= scale; v.w *= scale;
        *(float4*)&QP[r * KST + c4 * 4] = v;
    }
    __syncthreads();

    uint32_t qf[8][4];
    #pragma unroll
    for (int ks = 0; ks < 8; ks++) {
        int kb = ks * 8;
        qf[ks][0] = f2tf32(QP[(wr + gq    ) * KST + kb + gt    ]);
        qf[ks][1] = f2tf32(QP[(wr + gq + 8) * KST + kb + gt    ]);
        qf[ks][2] = f2tf32(QP[(wr + gq    ) * KST + kb + gt + 4]);
        qf[ks][3] = f2tf32(QP[(wr + gq + 8) * KST + kb + gt + 4]);
    }
    __syncthreads();

    float* Ps = QP + warp * 16 * KST;

    float m0 = -1e30f, m1 = -1e30f, l0 = 0.f, l1 = 0.f;
    float oacc[8][4];
    #pragma unroll
    for (int nf = 0; nf < 8; nf++)
        #pragma unroll
        for (int j = 0; j < 4; j++) oacc[nf][j] = 0.f;

    for (int kt = 0; kt < NSEQ / 64; kt++) {
        cp_wait<0>();
        __syncthreads();
        if (kt + 1 < NSEQ / 64) load_kv(kt + 1, (kt + 1) & 1);
        const float* Kb = Ks + (kt & 1) * 64 * KST;
        const float* Vb = Vs + (kt & 1) * 64 * VST;

        float sacc[8][4];
        #pragma unroll
        for (int nf = 0; nf < 8; nf++)
            #pragma unroll
            for (int j = 0; j < 4; j++) sacc[nf][j] = 0.f;

        #pragma unroll
        for (int ks = 0; ks < 8; ks++) {
            int kb = ks * 8;
            #pragma unroll
            for (int nf = 0; nf < 8; nf++) {
                uint32_t b0 = f2tf32(Kb[(nf * 8 + gq) * KST + kb + gt    ]);
                uint32_t b1 = f2tf32(Kb[(nf * 8 + gq) * KST + kb + gt + 4]);
                mma_tf32(sacc[nf], qf[ks][0], qf[ks][1], qf[ks][2], qf[ks][3], b0, b1);
            }
        }

        float mx0 = -1e30f, mx1 = -1e30f;
        #pragma unroll
        for (int nf = 0; nf < 8; nf++) {
            mx0 = fmaxf(mx0, fmaxf(sacc[nf][0], sacc[nf][1]));
            mx1 = fmaxf(mx1, fmaxf(sacc[nf][2], sacc[nf][3]));
        }
        mx0 = fmaxf(mx0, __shfl_xor_sync(0xffffffffu, mx0, 1));
        mx0 = fmaxf(mx0, __shfl_xor_sync(0xffffffffu, mx0, 2));
        mx1 = fmaxf(mx1, __shfl_xor_sync(0xffffffffu, mx1, 1));
        mx1 = fmaxf(mx1, __shfl_xor_sync(0xffffffffu, mx1, 2));

        float mn0 = fmaxf(m0, mx0), mn1 = fmaxf(m1, mx1);
        float alpha0 = __expf(m0 - mn0), alpha1 = __expf(m1 - mn1);
        m0 = mn0; m1 = mn1;

        float sum0 = 0.f, sum1 = 0.f;
        #pragma unroll
        for (int nf = 0; nf < 8; nf++) {
            float p0 = __expf(sacc[nf][0] - mn0);
            float p1 = __expf(sacc[nf][1] - mn0);
            float p2 = __expf(sacc[nf][2] - mn1);
            float p3 = __expf(sacc[nf][3] - mn1);
            sum0 += p0 + p1; sum1 += p2 + p3;
            *(float2*)&Ps[ gq      * KST + nf * 8 + gt * 2] = make_float2(p0, p1);
            *(float2*)&Ps[(gq + 8) * KST + nf * 8 + gt * 2] = make_float2(p2, p3);
        }
        sum0 += __shfl_xor_sync(0xffffffffu, sum0, 1);
        sum0 += __shfl_xor_sync(0xffffffffu, sum0, 2);
        sum1 += __shfl_xor_sync(0xffffffffu, sum1, 1);
        sum1 += __shfl_xor_sync(0xffffffffu, sum1, 2);
        l0 = l0 * alpha0 + sum0;
        l1 = l1 * alpha1 + sum1;

        #pragma unroll
        for (int nf = 0; nf < 8; nf++) {
            oacc[nf][0] *= alpha0; oacc[nf][1] *= alpha0;
            oacc[nf][2] *= alpha1; oacc[nf][3] *= alpha1;
        }
        __syncwarp();

        #pragma unroll
        for (int ks = 0; ks < 8; ks++) {
            int kb = ks * 8;
            uint32_t a0 = f2tf32(Ps[ gq      * KST + kb + gt    ]);
            uint32_t a1 = f2tf32(Ps[(gq + 8) * KST + kb + gt    ]);
            uint32_t a2 = f2tf32(Ps[ gq      * KST + kb + gt + 4]);
            uint32_t a3 = f2tf32(Ps[(gq + 8) * KST + kb + gt + 4]);
            #pragma unroll
            for (int nf = 0; nf < 8; nf++) {
                uint32_t b0 = f2tf32(Vb[(kb + gt    ) * VST + nf * 8 + gq]);
                uint32_t b1 = f2tf32(Vb[(kb + gt + 4) * VST + nf * 8 + gq]);
                mma_tf32(oacc[nf], a0, a1, a2, a3, b0, b1);
            }
        }
        __syncwarp();
    }

    float invl0 = 1.0f / l0, invl1 = 1.0f / l1;
    int r0 = q_tok0 + wr + gq;
    #pragma unroll
    for (int nf = 0; nf < 8; nf++) {
        int c = h * HD + nf * 8 + gt * 2;
        *(float2*)&o[(size_t) r0      * DIM + c] = make_float2(
            round_tf32(oacc[nf][0] * invl0), round_tf32(oacc[nf][1] * invl0));
        *(float2*)&o[(size_t)(r0 + 8) * DIM + c] = make_float2(
            round_tf32(oacc[nf][2] * invl1), round_tf32(oacc[nf][3] * invl1));
    }
}

// ---------------------------------------------------------------------------
// Launch
// ---------------------------------------------------------------------------
extern "C" void kernel_launch(void* const* d_in, const int* in_sizes, int n_in,
                              void* d_out, int out_size)
{
    const float* x      = (const float*)d_in[0];
    const float* ln1_g  = (const float*)d_in[1];
    const float* ln1_b  = (const float*)d_in[2];
    const float* w_qkv  = (const float*)d_in[3];
    const float* w_proj = (const float*)d_in[4];
    const float* b_proj = (const float*)d_in[5];
    const float* ln2_g  = (const float*)d_in[6];
    const float* ln2_b  = (const float*)d_in[7];
    const float* w_fc1  = (const float*)d_in[8];
    const float* b_fc1  = (const float*)d_in[9];
    const float* w_fc2  = (const float*)d_in[10];
    const float* b_fc2  = (const float*)d_in[11];
    float* out = (float*)d_out;

    float *p_h, *p_qkv, *p_o, *p_x1, *p_h2, *p_m;
    float *p_wq, *p_wp, *p_w1, *p_w2;
    cudaGetSymbolAddress((void**)&p_h,   g_h);
    cudaGetSymbolAddress((void**)&p_qkv, g_qkv);
    cudaGetSymbolAddress((void**)&p_o,   g_o);
    cudaGetSymbolAddress((void**)&p_x1,  g_x1);
    cudaGetSymbolAddress((void**)&p_h2,  g_h2);
    cudaGetSymbolAddress((void**)&p_m,   g_m);
    cudaGetSymbolAddress((void**)&p_wq,  g_wq);
    cudaGetSymbolAddress((void**)&p_wp,  g_wp);
    cudaGetSymbolAddress((void**)&p_w1,  g_w1);
    cudaGetSymbolAddress((void**)&p_w2,  g_w2);

    const int attn_smem = ATTN_SMEM_FLOATS * (int)sizeof(float); // ~87 KB
    cudaFuncSetAttribute(attn_tc,
                         cudaFuncAttributeMaxDynamicSharedMemorySize, attn_smem);
    cudaFuncSetAttribute(gemm_tc<0>,
                         cudaFuncAttributeMaxDynamicSharedMemorySize, GEMM_SMEM_BYTES);
    cudaFuncSetAttribute(gemm_tc<1>,
                         cudaFuncAttributeMaxDynamicSharedMemorySize, GEMM_SMEM_BYTES);
    cudaFuncSetAttribute(gemm_tc<2>,
                         cudaFuncAttributeMaxDynamicSharedMemorySize, GEMM_SMEM_BYTES);

    // 0. Pre-round weights to tf32 (once per launch)
    {
        int n;
        n = DIM * H3  / 4; round_w_kernel<<<(n + 255) / 256, 256>>>((const float4*)w_qkv,  (float4*)p_wq, n);
        n = DIM * DIM / 4; round_w_kernel<<<(n + 255) / 256, 256>>>((const float4*)w_proj, (float4*)p_wp, n);
        n = DIM * HID / 4; round_w_kernel<<<(n + 255) / 256, 256>>>((const float4*)w_fc1,  (float4*)p_w1, n);
        n = HID * DIM / 4; round_w_kernel<<<(n + 255) / 256, 256>>>((const float4*)w_fc2,  (float4*)p_w2, n);
    }

    // 1. LN1 (tf32-rounded out)
    ln_kernel<<<TOK, 256>>>(x, ln1_g, ln1_b, p_h);
    // 2. QKV GEMM: [4096,768] @ [768,2304]
    gemm_tc<0><<<dim3(H3 / 128, TOK / 128), 128, GEMM_SMEM_BYTES>>>(
        p_h, p_wq, nullptr, nullptr, p_qkv, TOK, H3, DIM);
    // 3. Attention (tensor cores, tf32-rounded out)
    attn_tc<<<dim3(NSEQ / 64, NHEAD, 2), 128, attn_smem>>>(p_qkv, p_o);
    // 4. Proj GEMM + bias + residual(x) -> full fp32
    gemm_tc<1><<<dim3(DIM / 128, TOK / 128), 128, GEMM_SMEM_BYTES>>>(
        p_o, p_wp, b_proj, x, p_x1, TOK, DIM, DIM);
    // 5. LN2 (tf32-rounded out)
    ln_kernel<<<TOK, 256>>>(p_x1, ln2_g, ln2_b, p_h2);
    // 6. FC1 GEMM + bias + GELU (tf32-rounded out)
    gemm_tc<2><<<dim3(HID / 128, TOK / 128), 128, GEMM_SMEM_BYTES>>>(
        p_h2, p_w1, b_fc1, nullptr, p_m, TOK, HID, DIM);
    // 7. FC2 GEMM + bias + residual(x1) -> d_out (full fp32)
    gemm_tc<1><<<dim3(DIM / 128, TOK / 128), 128, GEMM_SMEM_BYTES>>>(
        p_m, p_w2, b_fc2, p_x1, out, TOK, DIM, HID);
}

// round 8
// speedup vs baseline: 4.2515x; 1.2945x over previous
#include <cuda_runtime.h>
#include <cuda_fp16.h>
#include <math.h>
#include <stdint.h>

#define TOK   4096
#define NSEQ  2048
#define DIM   768
#define H3    2304
#define HID   3072
#define NHEAD 12
#define HD    64

__device__ __align__(128) __half g_h  [TOK * DIM];   // LN1 out (fp16)
__device__ __align__(128) float  g_qkv[TOK * H3];    // qkv (fp32, attn input)
__device__ __align__(128) __half g_o  [TOK * DIM];   // attn out (fp16)
__device__ __align__(128) float  g_x1 [TOK * DIM];   // x + proj (fp32)
__device__ __align__(128) __half g_h2 [TOK * DIM];   // LN2 out (fp16)
__device__ __align__(128) __half g_m  [TOK * HID];   // gelu(fc1) (fp16)
// fp16 TRANSPOSED weights WT[n][k]
__device__ __align__(128) __half g_wq [H3 * DIM];
__device__ __align__(128) __half g_wp [DIM * DIM];
__device__ __align__(128) __half g_w1 [HID * DIM];
__device__ __align__(128) __half g_w2 [DIM * HID];

// ---------------- PTX helpers ----------------
__device__ __forceinline__ uint32_t f2tf32(float f) {
    uint32_t u; asm("cvt.rna.tf32.f32 %0, %1;" : "=r"(u) : "f"(f)); return u;
}
__device__ __forceinline__ void mma_tf32(float* d,
    uint32_t a0, uint32_t a1, uint32_t a2, uint32_t a3, uint32_t b0, uint32_t b1)
{
    asm volatile(
        "mma.sync.aligned.m16n8k8.row.col.f32.tf32.tf32.f32 "
        "{%0,%1,%2,%3}, {%4,%5,%6,%7}, {%8,%9}, {%0,%1,%2,%3};"
        : "+f"(d[0]), "+f"(d[1]), "+f"(d[2]), "+f"(d[3])
        : "r"(a0), "r"(a1), "r"(a2), "r"(a3), "r"(b0), "r"(b1));
}
__device__ __forceinline__ void mma_f16(float* d,
    uint32_t a0, uint32_t a1, uint32_t a2, uint32_t a3, uint32_t b0, uint32_t b1)
{
    asm volatile(
        "mma.sync.aligned.m16n8k16.row.col.f32.f16.f16.f32 "
        "{%0,%1,%2,%3}, {%4,%5,%6,%7}, {%8,%9}, {%0,%1,%2,%3};"
        : "+f"(d[0]), "+f"(d[1]), "+f"(d[2]), "+f"(d[3])
        : "r"(a0), "r"(a1), "r"(a2), "r"(a3), "r"(b0), "r"(b1));
}
__device__ __forceinline__ void cp_async16(uint32_t s, const void* g) {
    asm volatile("cp.async.cg.shared.global [%0], [%1], 16;" :: "r"(s), "l"(g));
}
__device__ __forceinline__ void cp_commit() { asm volatile("cp.async.commit_group;" ::); }
template<int N> __device__ __forceinline__ void cp_wait() {
    asm volatile("cp.async.wait_group %0;" :: "n"(N));
}
__device__ __forceinline__ uint32_t smem_u32(const void* p) {
    uint32_t a;
    asm("{ .reg .u64 t; cvta.to.shared.u64 t, %1; cvt.u32.u64 %0, t; }" : "=r"(a) : "l"(p));
    return a;
}

// -------- weight convert+transpose: dst[n][k] = fp16(src[k][n]) --------
__global__ __launch_bounds__(256) void trw_kernel(
    const float* __restrict__ src, __half* __restrict__ dst, int K, int N)
{
    __shared__ float t[32][33];
    int kb = blockIdx.y * 32, nb = blockIdx.x * 32;
    int tx = threadIdx.x & 31, ty = threadIdx.x >> 5;
    #pragma unroll
    for (int i = 0; i < 32; i += 8)
        t[ty + i][tx] = src[(size_t)(kb + ty + i) * N + nb + tx];
    __syncthreads();
    #pragma unroll
    for (int i = 0; i < 32; i += 8)
        dst[(size_t)(nb + ty + i) * K + kb + tx] = __float2half(t[tx][ty + i]);
}

// -------- LayerNorm (fp16 out) --------
__global__ __launch_bounds__(256) void ln_kernel(
    const float* __restrict__ x, const float* __restrict__ g,
    const float* __restrict__ b, __half* __restrict__ out)
{
    int row = blockIdx.x, t = threadIdx.x;
    const float* xr = x + row * DIM;
    float v0 = xr[t], v1 = xr[t + 256], v2 = xr[t + 512];
    float s = v0 + v1 + v2, q = v0 * v0 + v1 * v1 + v2 * v2;
    __shared__ float rs[8], rq[8];
    #pragma unroll
    for (int o = 16; o; o >>= 1) {
        s += __shfl_xor_sync(0xffffffffu, s, o);
        q += __shfl_xor_sync(0xffffffffu, q, o);
    }
    if ((t & 31) == 0) { rs[t >> 5] = s; rq[t >> 5] = q; }
    __syncthreads();
    __shared__ float smu, srstd;
    if (t == 0) {
        float S = 0.f, Q = 0.f;
        #pragma unroll
        for (int i = 0; i < 8; i++) { S += rs[i]; Q += rq[i]; }
        float mu = S * (1.0f / DIM), var = Q * (1.0f / DIM) - mu * mu;
        smu = mu; srstd = rsqrtf(var + 1e-5f);
    }
    __syncthreads();
    float mu = smu, r = srstd;
    __half* orow = out + row * DIM;
    orow[t]       = __float2half((v0 - mu) * r * g[t]       + b[t]);
    orow[t + 256] = __float2half((v1 - mu) * r * g[t + 256] + b[t + 256]);
    orow[t + 512] = __float2half((v2 - mu) * r * g[t + 512] + b[t + 512]);
}

// -------- fp16 tensor-core GEMM: C = A[M,K] @ BT[N,K]^T (+epilogue) --------
// CTA 128x128, BK=32 halfs, 128 threads = 4 warps (2x2), warp tile 64x64.
// m16n8k16; smem half-stride 40 (conflict-free); 3-stage cp.async.
// EPI: 0 none (float out), 1 bias+residual (float out), 2 bias+GELU (half out)
#define HST 40                          // halfs per smem row (32 + 8 pad)
#define HTILE_B (128 * HST * 2)         // 10240 bytes
#define HSTAGE_B (2 * HTILE_B)          // A + B = 20480
#define HSTAGES 3
#define HSMEM (HSTAGES * HSTAGE_B)      // 61440

template<int EPI, typename OT>
__global__ __launch_bounds__(128) void gemm_h(
    const __half* __restrict__ A, const __half* __restrict__ BT,
    const float* __restrict__ bias, const float* __restrict__ res,
    OT* __restrict__ C, int M, int N, int K)
{
    extern __shared__ char smem[];
    uint32_t sb = smem_u32(smem);

    int tid = threadIdx.x, lane = tid & 31, warp = tid >> 5;
    int wm = warp >> 1, wn = warp & 1;
    int gq = lane >> 2, gt = lane & 3;
    int row0 = blockIdx.y * 128, col0 = blockIdx.x * 128;

    float acc[4][8][4];
    #pragma unroll
    for (int mi = 0; mi < 4; mi++)
        #pragma unroll
        for (int nf = 0; nf < 8; nf++)
            #pragma unroll
            for (int j = 0; j < 4; j++) acc[mi][nf][j] = 0.f;

    auto load_tile = [&](int kt, int buf) {
        uint32_t ab = sb + buf * HSTAGE_B;
        int k0 = kt * 32;
        #pragma unroll
        for (int i = 0; i < 4; i++) {
            int e = tid + i * 128;          // 0..511
            int r = e >> 2, c8 = e & 3;     // 4 x 8-half chunks per row
            cp_async16(ab + r * (HST * 2) + c8 * 16,
                       A + (size_t)(row0 + r) * K + k0 + c8 * 8);
        }
        #pragma unroll
        for (int i = 0; i < 4; i++) {
            int e = tid + i * 128;
            int r = e >> 2, c8 = e & 3;
            cp_async16(ab + HTILE_B + r * (HST * 2) + c8 * 16,
                       BT + (size_t)(col0 + r) * K + k0 + c8 * 8);
        }
        cp_commit();
    };

    int nt = K / 32;
    load_tile(0, 0);
    load_tile(1, 1);

    for (int t = 0; t < nt; t++) {
        cp_wait<HSTAGES - 2>();
        __syncthreads();
        if (t + 2 < nt) load_tile(t + 2, (t + 2) % HSTAGES);
        int buf = t % HSTAGES;

        const uint32_t* Au = (const uint32_t*)(smem + buf * HSTAGE_B);
        const uint32_t* Bu = (const uint32_t*)(smem + buf * HSTAGE_B + HTILE_B);

        #pragma unroll
        for (int ks = 0; ks < 2; ks++) {
            int kw = ks * 8;                 // word offset within 20-word row
            uint32_t af[4][4];
            #pragma unroll
            for (int mi = 0; mi < 4; mi++) {
                int r = wm * 64 + mi * 16 + gq;
                af[mi][0] = Au[ r      * 20 + kw + gt    ];
                af[mi][1] = Au[(r + 8) * 20 + kw + gt    ];
                af[mi][2] = Au[ r      * 20 + kw + gt + 4];
                af[mi][3] = Au[(r + 8) * 20 + kw + gt + 4];
            }
            uint32_t bf[8][2];
            #pragma unroll
            for (int nf = 0; nf < 8; nf++) {
                int n = wn * 64 + nf * 8 + gq;
                bf[nf][0] = Bu[n * 20 + kw + gt    ];
                bf[nf][1] = Bu[n * 20 + kw + gt + 4];
            }
            #pragma unroll
            for (int mi = 0; mi < 4; mi++)
                #pragma unroll
                for (int nf = 0; nf < 8; nf++)
                    mma_f16(acc[mi][nf],
                            af[mi][0], af[mi][1], af[mi][2], af[mi][3],
                            bf[nf][0], bf[nf][1]);
        }
    }

    #pragma unroll
    for (int mi = 0; mi < 4; mi++) {
        int r = row0 + wm * 64 + mi * 16 + gq;
        #pragma unroll
        for (int nf = 0; nf < 8; nf++) {
            int c = col0 + wn * 64 + nf * 8 + gt * 2;
            float v0 = acc[mi][nf][0], v1 = acc[mi][nf][1];
            float v2 = acc[mi][nf][2], v3 = acc[mi][nf][3];
            if (EPI >= 1) {
                float b0 = bias[c], b1 = bias[c + 1];
                v0 += b0; v1 += b1; v2 += b0; v3 += b1;
            }
            if (EPI == 1) {
                const float2 r01 = *(const float2*)&res[(size_t) r      * N + c];
                const float2 r23 = *(const float2*)&res[(size_t)(r + 8) * N + c];
                v0 += r01.x; v1 += r01.y; v2 += r23.x; v3 += r23.y;
            }
            if (EPI == 2) {
                v0 = 0.5f * v0 * (1.0f + erff(v0 * 0.70710678118f));
                v1 = 0.5f * v1 * (1.0f + erff(v1 * 0.70710678118f));
                v2 = 0.5f * v2 * (1.0f + erff(v2 * 0.70710678118f));
                v3 = 0.5f * v3 * (1.0f + erff(v3 * 0.70710678118f));
                __half* Ch = (__half*)C;
                *(__half2*)&Ch[(size_t) r      * N + c] = __floats2half2_rn(v0, v1);
                *(__half2*)&Ch[(size_t)(r + 8) * N + c] = __floats2half2_rn(v2, v3);
            } else {
                float* Cf = (float*)C;
                *(float2*)&Cf[(size_t) r      * N + c] = make_float2(v0, v1);
                *(float2*)&Cf[(size_t)(r + 8) * N + c] = make_float2(v2, v3);
            }
        }
    }
}

// -------- flash attention (tf32 mma, unchanged math; fp16 output) --------
#define KST 68
#define VST 72
#define SM_K  (64 * KST)
#define SM_V  (SM_K + 2 * 64 * KST)
#define ATTN_SMEM_FLOATS (SM_V + 2 * 64 * VST)

__global__ __launch_bounds__(128) void attn_tc(
    const float* __restrict__ qkv, __half* __restrict__ o)
{
    extern __shared__ float sm[];
    float* QP = sm;
    float* Ks = sm + SM_K;
    float* Vs = sm + SM_V;
    int tid = threadIdx.x, lane = tid & 31, warp = tid >> 5;
    int gq = lane >> 2, gt = lane & 3, wr = warp * 16;
    int qt = blockIdx.x, h = blockIdx.y, b = blockIdx.z;
    int q_tok0 = b * NSEQ + qt * 64;
    int qcol = h * HD, kcol = DIM + h * HD, vcol = 2 * DIM + h * HD;
    const float scale = 0.125f;

    auto load_kv = [&](int kt, int buf) {
        int k_tok0 = b * NSEQ + kt * 64;
        #pragma unroll
        for (int i = 0; i < 8; i++) {
            int e = tid + i * 128, r = e >> 4, c4 = e & 15;
            cp_async16(smem_u32(&Ks[buf * 64 * KST + r * KST + c4 * 4]),
                       qkv + (size_t)(k_tok0 + r) * H3 + kcol + c4 * 4);
            cp_async16(smem_u32(&Vs[buf * 64 * VST + r * VST + c4 * 4]),
                       qkv + (size_t)(k_tok0 + r) * H3 + vcol + c4 * 4);
        }
        cp_commit();
    };

    load_kv(0, 0);
    #pragma unroll
    for (int i = 0; i < 8; i++) {
        int e = tid + i * 128, r = e >> 4, c4 = e & 15;
        float4 v = *(const float4*)(qkv + (size_t)(q_tok0 + r) * H3 + qcol + c4 * 4);
        v.x *= scale; v.y *= scale; v.z *= scale; v.w *= scale;
        *(float4*)&QP[r * KST + c4 * 4] = v;
    }
    __syncthreads();
    uint32_t qf[8][4];
    #pragma unroll
    for (int ks = 0; ks < 8; ks++) {
        int kb = ks * 8;
        qf[ks][0] = f2tf32(QP[(wr + gq    ) * KST + kb + gt    ]);
        qf[ks][1] = f2tf32(QP[(wr + gq + 8) * KST + kb + gt    ]);
        qf[ks][2] = f2tf32(QP[(wr + gq    ) * KST + kb + gt + 4]);
        qf[ks][3] = f2tf32(QP[(wr + gq + 8) * KST + kb + gt + 4]);
    }
    __syncthreads();
    float* Ps = QP + warp * 16 * KST;
    float m0 = -1e30f, m1 = -1e30f, l0 = 0.f, l1 = 0.f;
    float oacc[8][4];
    #pragma unroll
    for (int nf = 0; nf < 8; nf++)
        #pragma unroll
        for (int j = 0; j < 4; j++) oacc[nf][j] = 0.f;

    for (int kt = 0; kt < NSEQ / 64; kt++) {
        cp_wait<0>();
        __syncthreads();
        if (kt + 1 < NSEQ / 64) load_kv(kt + 1, (kt + 1) & 1);
        const float* Kb = Ks + (kt & 1) * 64 * KST;
        const float* Vb = Vs + (kt & 1) * 64 * VST;

        float sacc[8][4];
        #pragma unroll
        for (int nf = 0; nf < 8; nf++)
            #pragma unroll
            for (int j = 0; j < 4; j++) sacc[nf][j] = 0.f;
        #pragma unroll
        for (int ks = 0; ks < 8; ks++) {
            int kb = ks * 8;
            #pragma unroll
            for (int nf = 0; nf < 8; nf++) {
                uint32_t b0 = f2tf32(Kb[(nf * 8 + gq) * KST + kb + gt    ]);
                uint32_t b1 = f2tf32(Kb[(nf * 8 + gq) * KST + kb + gt + 4]);
                mma_tf32(sacc[nf], qf[ks][0], qf[ks][1], qf[ks][2], qf[ks][3], b0, b1);
            }
        }
        float mx0 = -1e30f, mx1 = -1e30f;
        #pragma unroll
        for (int nf = 0; nf < 8; nf++) {
            mx0 = fmaxf(mx0, fmaxf(sacc[nf][0], sacc[nf][1]));
            mx1 = fmaxf(mx1, fmaxf(sacc[nf][2], sacc[nf][3]));
        }
        mx0 = fmaxf(mx0, __shfl_xor_sync(0xffffffffu, mx0, 1));
        mx0 = fmaxf(mx0, __shfl_xor_sync(0xffffffffu, mx0, 2));
        mx1 = fmaxf(mx1, __shfl_xor_sync(0xffffffffu, mx1, 1));
        mx1 = fmaxf(mx1, __shfl_xor_sync(0xffffffffu, mx1, 2));
        float mn0 = fmaxf(m0, mx0), mn1 = fmaxf(m1, mx1);
        float alpha0 = __expf(m0 - mn0), alpha1 = __expf(m1 - mn1);
        m0 = mn0; m1 = mn1;
        float sum0 = 0.f, sum1 = 0.f;
        #pragma unroll
        for (int nf = 0; nf < 8; nf++) {
            float p0 = __expf(sacc[nf][0] - mn0), p1 = __expf(sacc[nf][1] - mn0);
            float p2 = __expf(sacc[nf][2] - mn1), p3 = __expf(sacc[nf][3] - mn1);
            sum0 += p0 + p1; sum1 += p2 + p3;
            *(float2*)&Ps[ gq      * KST + nf * 8 + gt * 2] = make_float2(p0, p1);
            *(float2*)&Ps[(gq + 8) * KST + nf * 8 + gt * 2] = make_float2(p2, p3);
        }
        sum0 += __shfl_xor_sync(0xffffffffu, sum0, 1);
        sum0 += __shfl_xor_sync(0xffffffffu, sum0, 2);
        sum1 += __shfl_xor_sync(0xffffffffu, sum1, 1);
        sum1 += __shfl_xor_sync(0xffffffffu, sum1, 2);
        l0 = l0 * alpha0 + sum0;
        l1 = l1 * alpha1 + sum1;
        #pragma unroll
        for (int nf = 0; nf < 8; nf++) {
            oacc[nf][0] *= alpha0; oacc[nf][1] *= alpha0;
            oacc[nf][2] *= alpha1; oacc[nf][3] *= alpha1;
        }
        __syncwarp();
        #pragma unroll
        for (int ks = 0; ks < 8; ks++) {
            int kb = ks * 8;
            uint32_t a0 = f2tf32(Ps[ gq      * KST + kb + gt    ]);
            uint32_t a1 = f2tf32(Ps[(gq + 8) * KST + kb + gt    ]);
            uint32_t a2 = f2tf32(Ps[ gq      * KST + kb + gt + 4]);
            uint32_t a3 = f2tf32(Ps[(gq + 8) * KST + kb + gt + 4]);
            #pragma unroll
            for (int nf = 0; nf < 8; nf++) {
                uint32_t b0 = f2tf32(Vb[(kb + gt    ) * VST + nf * 8 + gq]);
                uint32_t b1 = f2tf32(Vb[(kb + gt + 4) * VST + nf * 8 + gq]);
                mma_tf32(oacc[nf], a0, a1, a2, a3, b0, b1);
            }
        }
        __syncwarp();
    }
    float invl0 = 1.0f / l0, invl1 = 1.0f / l1;
    int r0 = q_tok0 + wr + gq;
    #pragma unroll
    for (int nf = 0; nf < 8; nf++) {
        int c = h * HD + nf * 8 + gt * 2;
        *(__half2*)&o[(size_t) r0      * DIM + c] =
            __floats2half2_rn(oacc[nf][0] * invl0, oacc[nf][1] * invl0);
        *(__half2*)&o[(size_t)(r0 + 8) * DIM + c] =
            __floats2half2_rn(oacc[nf][2] * invl1, oacc[nf][3] * invl1);
    }
}

// ---------------- Launch ----------------
extern "C" void kernel_launch(void* const* d_in, const int* in_sizes, int n_in,
                              void* d_out, int out_size)
{
    const float* x      = (const float*)d_in[0];
    const float* ln1_g  = (const float*)d_in[1];
    const float* ln1_b  = (const float*)d_in[2];
    const float* w_qkv  = (const float*)d_in[3];
    const float* w_proj = (const float*)d_in[4];
    const float* b_proj = (const float*)d_in[5];
    const float* ln2_g  = (const float*)d_in[6];
    const float* ln2_b  = (const float*)d_in[7];
    const float* w_fc1  = (const float*)d_in[8];
    const float* b_fc1  = (const float*)d_in[9];
    const float* w_fc2  = (const float*)d_in[10];
    const float* b_fc2  = (const float*)d_in[11];
    float* out = (float*)d_out;

    __half *p_h, *p_o, *p_h2, *p_m, *p_wq, *p_wp, *p_w1, *p_w2;
    float  *p_qkv, *p_x1;
    cudaGetSymbolAddress((void**)&p_h,   g_h);
    cudaGetSymbolAddress((void**)&p_qkv, g_qkv);
    cudaGetSymbolAddress((void**)&p_o,   g_o);
    cudaGetSymbolAddress((void**)&p_x1,  g_x1);
    cudaGetSymbolAddress((void**)&p_h2,  g_h2);
    cudaGetSymbolAddress((void**)&p_m,   g_m);
    cudaGetSymbolAddress((void**)&p_wq,  g_wq);
    cudaGetSymbolAddress((void**)&p_wp,  g_wp);
    cudaGetSymbolAddress((void**)&p_w1,  g_w1);
    cudaGetSymbolAddress((void**)&p_w2,  g_w2);

    const int attn_smem = ATTN_SMEM_FLOATS * (int)sizeof(float);
    cudaFuncSetAttribute(attn_tc, cudaFuncAttributeMaxDynamicSharedMemorySize, attn_smem);
    cudaFuncSetAttribute((gemm_h<0, float>),  cudaFuncAttributeMaxDynamicSharedMemorySize, HSMEM);
    cudaFuncSetAttribute((gemm_h<1, float>),  cudaFuncAttributeMaxDynamicSharedMemorySize, HSMEM);
    cudaFuncSetAttribute((gemm_h<2, __half>), cudaFuncAttributeMaxDynamicSharedMemorySize, HSMEM);

    // 0. weights -> fp16, transposed WT[n][k]
    trw_kernel<<<dim3(H3 / 32,  DIM / 32), 256>>>(w_qkv,  p_wq, DIM, H3);
    trw_kernel<<<dim3(DIM / 32, DIM / 32), 256>>>(w_proj, p_wp, DIM, DIM);
    trw_kernel<<<dim3(HID / 32, DIM / 32), 256>>>(w_fc1,  p_w1, DIM, HID);
    trw_kernel<<<dim3(DIM / 32, HID / 32), 256>>>(w_fc2,  p_w2, HID, DIM);

    // 1. LN1 -> fp16
    ln_kernel<<<TOK, 256>>>(x, ln1_g, ln1_b, p_h);
    // 2. QKV GEMM (fp16 in, fp32 out)
    gemm_h<0, float><<<dim3(H3 / 128, TOK / 128), 128, HSMEM>>>(
        p_h, p_wq, nullptr, nullptr, p_qkv, TOK, H3, DIM);
    // 3. Attention (fp32 in, fp16 out)
    attn_tc<<<dim3(NSEQ / 64, NHEAD, 2), 128, attn_smem>>>(p_qkv, p_o);
    // 4. Proj + bias + residual(x) -> fp32
    gemm_h<1, float><<<dim3(DIM / 128, TOK / 128), 128, HSMEM>>>(
        p_o, p_wp, b_proj, x, p_x1, TOK, DIM, DIM);
    // 5. LN2 -> fp16
    ln_kernel<<<TOK, 256>>>(p_x1, ln2_g, ln2_b, p_h2);
    // 6. FC1 + bias + GELU -> fp16
    gemm_h<2, __half><<<dim3(HID / 128, TOK / 128), 128, HSMEM>>>(
        p_h2, p_w1, b_fc1, nullptr, p_m, TOK, HID, DIM);
    // 7. FC2 + bias + residual(x1) -> out (fp32)
    gemm_h<1, float><<<dim3(DIM / 128, TOK / 128), 128, HSMEM>>>(
        p_m, p_w2, b_fc2, p_x1, out, TOK, DIM, HID);
}